// round 14
// baseline (speedup 1.0000x reference)
#include <cuda_runtime.h>
#include <cuda_fp16.h>
#include <math.h>
#include <stdint.h>

#define BB 8
#define CC 256
#define CI 128
#define NPIX 4096
#define NPOOL 1024
#define WD 64
#define BN_EPS 1e-5f

// ---------------- scratch (__device__ globals, no allocations) ----------------
__device__ __align__(16) __half d_x2  [(size_t)BB * NPIX * (2 * CC)];   // [b][n][hi|lo]
__device__ __align__(16) __half d_w2all[(size_t)3 * CI * 2 * CC];       // theta|phi|g: [ci][hi|lo]
__device__ __align__(16) __half d_Ww1 [(size_t)CC * CI];                // [c][ci] single fp16
__device__ __align__(16) __half d_th2 [(size_t)BB * NPIX * (2 * CI)];   // [b][n][hi|lo]
__device__ __align__(16) __half d_phiP2[(size_t)BB * NPOOL * (2 * CI)]; // [b][m][hi|lo]
__device__ __align__(16) __half d_gPh [(size_t)BB * CI * NPOOL];        // [b][ci][m] single fp16
__device__ __align__(16) __half d_y1  [(size_t)BB * NPIX * CI];         // [b][n][ci] single fp16

// ---------------- helpers -------------------------------------------------------
__device__ __forceinline__ uint32_t smem_u32(const void* p) {
    uint32_t a;
    asm("{ .reg .u64 t; cvta.to.shared.u64 t, %1; cvt.u32.u64 %0, t; }" : "=r"(a) : "l"(p));
    return a;
}
__device__ __forceinline__ uint32_t pack_h2(__half a, __half b) {
    __half2 h(a, b);
    return *(uint32_t*)&h;
}
#define CP16(dst, src) asm volatile("cp.async.ca.shared.global [%0], [%1], 16;" :: "r"(dst), "l"(src))
#define CP_COMMIT()    asm volatile("cp.async.commit_group;" ::: "memory")
#define CP_WAIT1()     asm volatile("cp.async.wait_group 1;" ::: "memory")
#define CP_WAIT0()     asm volatile("cp.async.wait_group 0;" ::: "memory")

__device__ __forceinline__ void ldsm_x4(uint32_t* r, uint32_t addr) {
    asm volatile("ldmatrix.sync.aligned.m8n8.x4.shared.b16 {%0,%1,%2,%3}, [%4];"
                 : "=r"(r[0]), "=r"(r[1]), "=r"(r[2]), "=r"(r[3]) : "r"(addr));
}
__device__ __forceinline__ void ldsm_x2(uint32_t* r, uint32_t addr) {
    asm volatile("ldmatrix.sync.aligned.m8n8.x2.shared.b16 {%0,%1}, [%2];"
                 : "=r"(r[0]), "=r"(r[1]) : "r"(addr));
}
__device__ __forceinline__ void mma16816(float* c, const uint32_t* a, const uint32_t* b) {
    asm volatile("mma.sync.aligned.m16n8k16.row.col.f32.f16.f16.f32 "
                 "{%0,%1,%2,%3}, {%4,%5,%6,%7}, {%8,%9}, {%0,%1,%2,%3};"
                 : "+f"(c[0]), "+f"(c[1]), "+f"(c[2]), "+f"(c[3])
                 : "r"(a[0]), "r"(a[1]), "r"(a[2]), "r"(a[3]), "r"(b[0]), "r"(b[1]));
}

// ============ generic warp-mma GEMM with split-pass K slices =====================
#define STG_BYTES 20480
#define SB_OFF    10240

// MODE 4: out-GEMM, 1 pass (W single, y single). ldK=128 both, nchunks=4.
// MODE 5: merged projections. theta/phi: 3 passes (nch=24); g: 2 passes (nch=16).
template <int MODE>
__global__ __launch_bounds__(256) void mma_gemm(
    const __half* __restrict__ A, const __half* __restrict__ B,
    size_t sAb, size_t sBb,
    float* OF, size_t sOb, int ldO,
    const float* __restrict__ p0, const float* __restrict__ p1,
    const float* __restrict__ p2, const float* __restrict__ p3,
    const float* __restrict__ p4, const float* __restrict__ p5)
{
    constexpr int ldKA = (MODE == 5) ? 512 : 128;
    constexpr int ldKB = (MODE == 5) ? 512 : 128;

    __shared__ __align__(16) char sm[2 * STG_BYTES];
    const uint32_t smb = smem_u32(sm);
    const int tid = threadIdx.x;
    const int wid = tid >> 5, lid = tid & 31;
    const int b = (MODE == 5) ? (blockIdx.z & 7) : blockIdx.z;
    const int which = (MODE == 5) ? (blockIdx.z >> 3) : 0;
    const int nch = (MODE == 5) ? ((which == 2) ? 16 : 24) : 4;
    const int row0 = blockIdx.y * 128, col0 = blockIdx.x * 128;
    const int m_base = (wid & 1) * 64;
    const int n_base = (wid >> 1) * 32;

    const __half* At = A + sAb * b + (size_t)row0 * ldKA;
    const __half* Bt = B + sBb * (size_t)((MODE == 5) ? which : b) + (size_t)col0 * ldKB;

    const int r0i = tid >> 2, s0 = (tid & 3);
    const int r1i = (tid + 256) >> 2;
    const uint32_t d0 = (uint32_t)(r0i * 80 + s0 * 16);
    const uint32_t d1 = (uint32_t)(r1i * 80 + s0 * 16);
    const uint32_t aOff = (uint32_t)((m_base + (lid & 15)) * 80 + (lid >> 4) * 16);
    const uint32_t bOff = (uint32_t)((n_base + (lid & 7)) * 80 + ((lid >> 3) & 1) * 16);

    float acc[4][4][4] = {};

    auto issue = [&](int ch) {
        int aK, bK;
        if (MODE == 5) {
            const int p = ch / 8, kk = ch - p * 8;
            aK = (p == 1 ? 256 : 0) + kk * 32;
            bK = (p == 2 ? 256 : 0) + kk * 32;
        } else {
            aK = ch * 32;
            bK = ch * 32;
        }
        const uint32_t sa = smb + (uint32_t)(ch & 1) * STG_BYTES;
        const uint32_t sb2 = sa + SB_OFF;
        const __half* ga = At + aK;
        const __half* gb = Bt + bK;
        CP16(sa + d0, ga + (size_t)r0i * ldKA + s0 * 8);
        CP16(sa + d1, ga + (size_t)r1i * ldKA + s0 * 8);
        CP16(sb2 + d0, gb + (size_t)r0i * ldKB + s0 * 8);
        CP16(sb2 + d1, gb + (size_t)r1i * ldKB + s0 * 8);
    };

    issue(0);
    CP_COMMIT();
    for (int ch = 0; ch < nch; ++ch) {
        if (ch + 1 < nch) { issue(ch + 1); CP_COMMIT(); CP_WAIT1(); }
        else CP_WAIT0();
        __syncthreads();
        const uint32_t sa = smb + (uint32_t)(ch & 1) * STG_BYTES;
        const uint32_t sb2 = sa + SB_OFF;
#pragma unroll
        for (int ks = 0; ks < 2; ++ks) {
            uint32_t afr[4][4], bfr[4][2];
#pragma unroll
            for (int mi = 0; mi < 4; ++mi) ldsm_x4(afr[mi], sa + aOff + mi * 1280 + ks * 32);
#pragma unroll
            for (int ni = 0; ni < 4; ++ni) ldsm_x2(bfr[ni], sb2 + bOff + ni * 640 + ks * 32);
#pragma unroll
            for (int mi = 0; mi < 4; ++mi)
#pragma unroll
                for (int ni = 0; ni < 4; ++ni) mma16816(acc[mi][ni], afr[mi], bfr[ni]);
        }
        __syncthreads();
    }

    const int rl = lid >> 2;
    const int cl = 2 * (lid & 3);

    if constexpr (MODE == 4) {
        float* Ob = OF + sOb * b;
        const float* Xb = p5 + sOb * b;
#pragma unroll
        for (int mi = 0; mi < 4; ++mi)
#pragma unroll
            for (int half = 0; half < 2; ++half) {
                const int c = row0 + m_base + mi * 16 + rl + half * 8;
                const float inv = p1[c] * rsqrtf(p4[c] + BN_EPS);
                const float sh = (p0[c] - p3[c]) * inv + p2[c];
#pragma unroll
                for (int ni = 0; ni < 4; ++ni) {
                    const int cg = col0 + n_base + ni * 8 + cl;
                    float2 xv = *(const float2*)(Xb + (size_t)c * ldO + cg);
                    *(float2*)(Ob + (size_t)c * ldO + cg) = make_float2(
                        acc[mi][ni][2 * half + 0] * inv + sh + xv.x,
                        acc[mi][ni][2 * half + 1] * inv + sh + xv.y);
                }
            }
    } else { // MODE 5
        if (which == 0) {
            __half* Ob = d_th2 + (size_t)b * NPIX * (2 * CI);
#pragma unroll
            for (int mi = 0; mi < 4; ++mi)
#pragma unroll
                for (int ni = 0; ni < 4; ++ni) {
                    const int cg = col0 + n_base + ni * 8 + cl;
#pragma unroll
                    for (int half = 0; half < 2; ++half) {
                        float v0 = acc[mi][ni][2 * half + 0] + p0[cg];
                        float v1 = acc[mi][ni][2 * half + 1] + p0[cg + 1];
                        __half h0 = __float2half_rn(v0);
                        __half h1 = __float2half_rn(v1);
                        __half l0 = __float2half_rn(v0 - __half2float(h0));
                        __half l1 = __float2half_rn(v1 - __half2float(h1));
                        const int rg = row0 + m_base + mi * 16 + rl + half * 8;
                        __half* pr = Ob + (size_t)rg * (2 * CI) + cg;
                        *(uint32_t*)(pr)      = pack_h2(h0, h1);
                        *(uint32_t*)(pr + CI) = pack_h2(l0, l1);
                    }
                }
        } else {
            // Fused 2x2 maxpool epilogue (windows are tile-local).
            float (*stage)[33] = (float(*)[33])sm;
            const float* bias = (which == 1) ? p1 : p2;
            const int t_band = blockIdx.y;
#pragma unroll 1
            for (int cg2 = 0; cg2 < 4; ++cg2) {
                __syncthreads();
                if ((wid >> 1) == cg2) {
#pragma unroll
                    for (int mi = 0; mi < 4; ++mi)
#pragma unroll
                        for (int ni = 0; ni < 4; ++ni) {
                            const int r = m_base + mi * 16 + rl;
                            const int c = ni * 8 + cl;
                            stage[r][c]     = acc[mi][ni][0];
                            stage[r][c + 1] = acc[mi][ni][1];
                            stage[r + 8][c]     = acc[mi][ni][2];
                            stage[r + 8][c + 1] = acc[mi][ni][3];
                        }
                }
                __syncthreads();
                if (which == 1) {
                    const int c = tid & 31, pw0 = (tid >> 5) * 4;
                    const int ci = cg2 * 32 + c;
#pragma unroll
                    for (int j = 0; j < 4; ++j) {
                        const int pw = pw0 + j;
                        float v = fmaxf(fmaxf(stage[2 * pw][c], stage[2 * pw + 1][c]),
                                        fmaxf(stage[2 * pw + 64][c], stage[2 * pw + 65][c]))
                                  + bias[ci];
                        __half h = __float2half_rn(v);
                        __half l = __float2half_rn(v - __half2float(h));
                        const int m = t_band * 32 + pw;
                        __half* pr = d_phiP2 + ((size_t)b * NPOOL + m) * (2 * CI);
                        pr[ci] = h; pr[CI + ci] = l;
                    }
                } else {
                    const int pw = tid & 31, c0v = (tid >> 5) * 4;
                    const int m = t_band * 32 + pw;
#pragma unroll
                    for (int j = 0; j < 4; ++j) {
                        const int c = c0v + j, ci = cg2 * 32 + c;
                        float v = fmaxf(fmaxf(stage[2 * pw][c], stage[2 * pw + 1][c]),
                                        fmaxf(stage[2 * pw + 64][c], stage[2 * pw + 65][c]))
                                  + bias[ci];
                        d_gPh[((size_t)b * CI + ci) * NPOOL + m] = __float2half_rn(v);
                    }
                }
            }
        }
    }
}

// ============ flash kernel v4: FA2-style register-resident P =====================
// 16 warps = 8 m-groups (16 rows) x 2 n-groups (64 cols / k-slice).
// S: accS[8][4]; P packed in regs (pa[4][4]) = Y A-operand; Y partial per warp
// over its 64-col m-slice, all 128 ci (accY[16][4]); 2-way reduce at epilogue.
#define FL_PITCH1 144
#define FPP 272
#define FS_A    0
#define FS_B    (FS_A + 2 * 18432)          // 36864
#define FS_G    (FS_B + 2 * 18432)          // 73728
#define FS_RED  (FS_G + 34816)              // 108544
#define FS_RMAX (FS_RED + 2048)
#define FS_RSUM (FS_RMAX + 512)
#define FS_RSC  (FS_RSUM + 512)
#define FS_RBC  (FS_RSC + 512)
#define FS_ST   FS_A                        // epilogue staging overlay (64KB < 73728)
#define FL_SMEM (FS_RBC + 512)              // ~110.5 KB

__global__ __launch_bounds__(512, 1) void flash_kernel()
{
    extern __shared__ __align__(16) char sm[];
    const uint32_t smb = smem_u32(sm);
    float* red  = (float*)(sm + FS_RED);
    float* rmax = (float*)(sm + FS_RMAX);
    float* rsum = (float*)(sm + FS_RSUM);
    float* rsc  = (float*)(sm + FS_RSC);
    float* rbc  = (float*)(sm + FS_RBC);

    const int tid = threadIdx.x, wid = tid >> 5, lid = tid & 31;
    const int b = blockIdx.y;
    const int n0 = blockIdx.x * 128;
    const int mg = wid >> 1, ng = wid & 1;
    const int mrow = mg * 16;
    const int ncol = ng * 64;
    const int rl = lid >> 2, cl = 2 * (lid & 3);

    const __half* At = d_th2 + (size_t)b * NPIX * 256 + (size_t)n0 * 256;
    const __half* Pt = d_phiP2 + (size_t)b * NPOOL * 256;
    const __half* Gh = d_gPh + (size_t)b * CI * NPOOL;

    if (tid < 128) { rmax[tid] = -1e30f; rsum[tid] = 0.f; }
    __syncthreads();

    const uint32_t a1 = (uint32_t)((mrow + (lid & 15)) * FL_PITCH1 + (lid >> 4) * 16);
    const uint32_t b1 = (uint32_t)((ncol + (lid & 7)) * FL_PITCH1 + ((lid >> 3) & 1) * 16);
    // Y-phase G fragment base: rows = ci groups, k offset = ng*128 bytes (64 m * 2B)
    const uint32_t bY = (uint32_t)((lid & 7) * FPP + ((lid >> 3) & 1) * 16 + ng * 128);

    float accY[16][4] = {};

    for (int mt = 0; mt < 8; ++mt) {
        const int m0 = mt * 128;

        { // g tile (hi only), 128ci x 128m: 2048 vecs / 512 thr = 4 each
            const uint32_t gh = smb + FS_G;
#pragma unroll
            for (int t = 0; t < 4; ++t) {
                int j = tid + 512 * t;
                int row = j >> 4, seg = j & 15;
                CP16(gh + (uint32_t)(row * FPP + seg * 16),
                     Gh + (size_t)row * NPOOL + m0 + seg * 8);
            }
            CP_COMMIT();
        }

        auto issue1 = [&](int ch) {
            const int p = ch >> 1, kk = ch & 1;
            const int aK = (p == 1 ? 128 : 0) + kk * 64;
            const int bK = (p == 2 ? 128 : 0) + kk * 64;
            const uint32_t sa = smb + FS_A + (uint32_t)(ch & 1) * 18432;
            const uint32_t sbb = smb + FS_B + (uint32_t)(ch & 1) * 18432;
#pragma unroll
            for (int t = 0; t < 2; ++t) {
                int j = tid + 512 * t;
                int row = j >> 3, seg = j & 7;
                uint32_t dst = (uint32_t)(row * FL_PITCH1 + seg * 16);
                CP16(sa + dst, At + (size_t)row * 256 + aK + seg * 8);
                CP16(sbb + dst, Pt + (size_t)(m0 + row) * 256 + bK + seg * 8);
            }
            CP_COMMIT();
        };

        float accS[8][4] = {};
        issue1(0);
        for (int ch = 0; ch < 6; ++ch) {
            if (ch + 1 < 6) { issue1(ch + 1); CP_WAIT1(); }
            else CP_WAIT0();
            __syncthreads();
            const uint32_t sa = smb + FS_A + (uint32_t)(ch & 1) * 18432;
            const uint32_t sbb = smb + FS_B + (uint32_t)(ch & 1) * 18432;
#pragma unroll
            for (int ks = 0; ks < 4; ++ks) {
                uint32_t afr[4], bfr[8][2];
                ldsm_x4(afr, sa + a1 + ks * 32);
#pragma unroll
                for (int ni = 0; ni < 8; ++ni)
                    ldsm_x2(bfr[ni], sbb + b1 + ni * 8 * FL_PITCH1 + ks * 32);
#pragma unroll
                for (int ni = 0; ni < 8; ++ni) mma16816(accS[ni], afr, bfr[ni]);
            }
            __syncthreads();
        }
        // (final CP_WAIT0 + syncthreads also guarantee G tile is resident)

        // ---- online softmax (per-warp rows mrow..mrow+15, cols = its 64 k-slice) ----
#pragma unroll
        for (int half = 0; half < 2; ++half) {
            float v = -1e30f;
#pragma unroll
            for (int ni = 0; ni < 8; ++ni)
                v = fmaxf(v, fmaxf(accS[ni][2 * half], accS[ni][2 * half + 1]));
            v = fmaxf(v, __shfl_xor_sync(0xffffffffu, v, 1));
            v = fmaxf(v, __shfl_xor_sync(0xffffffffu, v, 2));
            if ((lid & 3) == 0)
                red[(mrow + rl + half * 8) * 2 + ng] = v;
        }
        __syncthreads();
        if (tid < 128) {
            float mOld = rmax[tid];
            float mNew = fmaxf(mOld, fmaxf(red[tid * 2], red[tid * 2 + 1]));
            rbc[tid] = mNew; rsc[tid] = __expf(mOld - mNew); rmax[tid] = mNew;
        }
        __syncthreads();

        const int r0 = mrow + rl, r1 = mrow + rl + 8;
        const float mb0 = rbc[r0], sc0 = rsc[r0];
        const float mb1 = rbc[r1], sc1 = rsc[r1];
#pragma unroll
        for (int cg = 0; cg < 16; ++cg) {
            accY[cg][0] *= sc0; accY[cg][1] *= sc0;
            accY[cg][2] *= sc1; accY[cg][3] *= sc1;
        }
        uint32_t pa[4][4];
        float s0 = 0.f, s1 = 0.f;
#pragma unroll
        for (int ni = 0; ni < 8; ++ni) {
            float e00 = __expf(accS[ni][0] - mb0);
            float e01 = __expf(accS[ni][1] - mb0);
            float e10 = __expf(accS[ni][2] - mb1);
            float e11 = __expf(accS[ni][3] - mb1);
            s0 += e00 + e01;
            s1 += e10 + e11;
            const int kt = ni >> 1, off = (ni & 1) * 2;
            pa[kt][off + 0] = pack_h2(__float2half_rn(e00), __float2half_rn(e01));
            pa[kt][off + 1] = pack_h2(__float2half_rn(e10), __float2half_rn(e11));
        }
        s0 += __shfl_xor_sync(0xffffffffu, s0, 1);
        s0 += __shfl_xor_sync(0xffffffffu, s0, 2);
        s1 += __shfl_xor_sync(0xffffffffu, s1, 1);
        s1 += __shfl_xor_sync(0xffffffffu, s1, 2);
        if ((lid & 3) == 0) {
            red[r0 * 2 + ng] = s0;
            red[r1 * 2 + ng] = s1;
        }
        __syncthreads();
        if (tid < 128)
            rsum[tid] = rsum[tid] * rsc[tid] + (red[tid * 2] + red[tid * 2 + 1]);

        // ---- phase 2: Y += P(regs) * g over warp's 64-col k-slice, all 128 ci ----
        {
            const uint32_t bb = smb + FS_G + bY;
#pragma unroll
            for (int ks = 0; ks < 4; ++ks) {
#pragma unroll
                for (int h = 0; h < 2; ++h) {
                    uint32_t bfr[8][2];
#pragma unroll
                    for (int i = 0; i < 8; ++i)
                        ldsm_x2(bfr[i], bb + (uint32_t)((h * 8 + i) * 8 * FPP) + ks * 32);
#pragma unroll
                    for (int i = 0; i < 8; ++i)
                        mma16816(accY[h * 8 + i], pa[ks], bfr[i]);
                }
            }
        }
        __syncthreads();   // protect G/red before next tile
    }

    // ---- epilogue: 2-way reduce across n-groups, normalize, write y fp16 ----
    float* stg = (float*)(sm + FS_ST);
    if (ng == 1) {
#pragma unroll
        for (int cg = 0; cg < 16; ++cg)
#pragma unroll
            for (int half = 0; half < 2; ++half) {
                const int r = mrow + rl + half * 8;
                *(float2*)(stg + r * 128 + cg * 8 + cl) =
                    make_float2(accY[cg][2 * half], accY[cg][2 * half + 1]);
            }
    }
    __syncthreads();
    if (ng == 0) {
        __half* Ob = d_y1 + (size_t)b * NPIX * CI + (size_t)n0 * CI;
#pragma unroll
        for (int half = 0; half < 2; ++half) {
            const int r = mrow + rl + half * 8;
            const float rinv = 1.f / rsum[r];
#pragma unroll
            for (int cg = 0; cg < 16; ++cg) {
                float2 p = *(const float2*)(stg + r * 128 + cg * 8 + cl);
                float v0 = (accY[cg][2 * half]     + p.x) * rinv;
                float v1 = (accY[cg][2 * half + 1] + p.y) * rinv;
                *(uint32_t*)(Ob + (size_t)r * CI + cg * 8 + cl) =
                    pack_h2(__float2half_rn(v0), __float2half_rn(v1));
            }
        }
    }
}

// ---------------- x transpose-convert: x[b][c][n] -> x2[b][n][hi|lo] -----------
__global__ __launch_bounds__(256) void conv_x_kernel(const float* __restrict__ x)
{
    __shared__ float t[32][33];
    const int b = blockIdx.z;
    const int c0 = blockIdx.y * 32, n0 = blockIdx.x * 32;
    const int tx = threadIdx.x, ty = threadIdx.y;
    const float* X = x + (size_t)b * CC * NPIX;
#pragma unroll
    for (int i = 0; i < 4; ++i)
        t[ty + 8 * i][tx] = X[(size_t)(c0 + ty + 8 * i) * NPIX + n0 + tx];
    __syncthreads();
    __half* O = d_x2 + (size_t)b * NPIX * (2 * CC);
#pragma unroll
    for (int i = 0; i < 4; ++i) {
        int n = n0 + ty + 8 * i;
        float v = t[tx][ty + 8 * i];
        __half h = __float2half_rn(v);
        __half l = __float2half_rn(v - __half2float(h));
        __half* row = O + (size_t)n * (2 * CC) + c0 + tx;
        row[0] = h; row[CC] = l;
    }
}

// ---------------- merged weight convert (all 4 weights, one launch) -------------
__global__ void conv_w_all(const float* __restrict__ th_w, const float* __restrict__ ph_w,
                           const float* __restrict__ g_w, const float* __restrict__ W_w)
{
    const int which = blockIdx.y;
    int idx = blockIdx.x * 256 + threadIdx.x;
    if (idx >= CI * CC) return;

    if (which == 3) {
        d_Ww1[idx] = __float2half_rn(W_w[idx]);
        return;
    }
    const float* src = which == 0 ? th_w : which == 1 ? ph_w : g_w;
    __half* dst = d_w2all + (size_t)which * CI * (2 * CC);
    int r = idx / CC, k = idx - r * CC;
    float v = src[idx];
    __half h = __float2half_rn(v);
    __half l = __float2half_rn(v - __half2float(h));
    __half* row = dst + (size_t)r * 2 * CC;
    row[k] = h;
    row[CC + k] = l;
}

// ---------------- launch ----------------------------------------------------------
template <typename T>
static T* sym_addr(const void* sym)
{
    void* p = nullptr;
    cudaGetSymbolAddress(&p, sym);
    return (T*)p;
}

extern "C" void kernel_launch(void* const* d_in, const int* in_sizes, int n_in,
                              void* d_out, int out_size)
{
    const float* x    = (const float*)d_in[0];
    const float* g_w  = (const float*)d_in[1];
    const float* g_b  = (const float*)d_in[2];
    const float* th_w = (const float*)d_in[3];
    const float* th_b = (const float*)d_in[4];
    const float* ph_w = (const float*)d_in[5];
    const float* ph_b = (const float*)d_in[6];
    const float* W_w  = (const float*)d_in[7];
    const float* W_b  = (const float*)d_in[8];
    const float* gam  = (const float*)d_in[9];
    const float* bet  = (const float*)d_in[10];
    const float* mea  = (const float*)d_in[11];
    const float* var  = (const float*)d_in[12];
    float* out = (float*)d_out;

    __half* x2    = sym_addr<__half>(d_x2);
    __half* w2all = sym_addr<__half>(d_w2all);
    __half* Ww1   = sym_addr<__half>(d_Ww1);
    __half* y1    = sym_addr<__half>(d_y1);

    cudaFuncSetAttribute(flash_kernel, cudaFuncAttributeMaxDynamicSharedMemorySize, FL_SMEM);

    conv_x_kernel<<<dim3(NPIX / 32, CC / 32, BB), dim3(32, 8)>>>(x);
    conv_w_all<<<dim3((CI * CC + 255) / 256, 4), 256>>>(th_w, ph_w, g_w, W_w);

    // merged projections with fused pool for phi/g: z = which*8 + b
    mma_gemm<5><<<dim3(1, 32, 24), 256>>>(
        x2, w2all, (size_t)NPIX * 512, (size_t)CI * 512,
        nullptr, 0, 0, th_b, ph_b, g_b, nullptr, nullptr, nullptr);

    flash_kernel<<<dim3(NPIX / 128, BB), 512, FL_SMEM>>>();

    // out GEMM: A=Ww1 single [c][ci], B=y1 single [n][ci], 1 pass
    mma_gemm<4><<<dim3(NPIX / 128, CC / 128, BB), 256>>>(
        Ww1, y1, 0, (size_t)NPIX * 128,
        out, (size_t)CC * NPIX, NPIX, W_b, gam, bet, mea, var, x);
}

// round 15
// speedup vs baseline: 1.0739x; 1.0739x over previous
#include <cuda_runtime.h>
#include <cuda_fp16.h>
#include <math.h>
#include <stdint.h>

#define BB 8
#define CC 256
#define CI 128
#define NPIX 4096
#define NPOOL 1024
#define WD 64
#define BN_EPS 1e-5f

// ---------------- scratch (__device__ globals, no allocations) ----------------
__device__ __align__(16) __half d_x2  [(size_t)BB * NPIX * (2 * CC)];   // [b][n][hi|lo]
__device__ __align__(16) __half d_w2all[(size_t)3 * CI * 2 * CC];       // theta|phi|g: [ci][hi|lo]
__device__ __align__(16) __half d_Ww1 [(size_t)CC * CI];                // [c][ci] single fp16
__device__ __align__(16) __half d_th2 [(size_t)BB * NPIX * (2 * CI)];   // [b][n][hi|lo]
__device__ __align__(16) __half d_phiP2[(size_t)BB * NPOOL * (2 * CI)]; // [b][m][hi|lo]
__device__ __align__(16) __half d_gPh [(size_t)BB * CI * NPOOL];        // [b][ci][m] single fp16
__device__ __align__(16) __half d_y1  [(size_t)BB * NPIX * CI];         // [b][n][ci] single fp16

// ---------------- helpers -------------------------------------------------------
__device__ __forceinline__ uint32_t smem_u32(const void* p) {
    uint32_t a;
    asm("{ .reg .u64 t; cvta.to.shared.u64 t, %1; cvt.u32.u64 %0, t; }" : "=r"(a) : "l"(p));
    return a;
}
__device__ __forceinline__ uint32_t pack_h2(__half a, __half b) {
    __half2 h(a, b);
    return *(uint32_t*)&h;
}
#define CP16(dst, src) asm volatile("cp.async.ca.shared.global [%0], [%1], 16;" :: "r"(dst), "l"(src))
#define CP_COMMIT()    asm volatile("cp.async.commit_group;" ::: "memory")
#define CP_WAIT1()     asm volatile("cp.async.wait_group 1;" ::: "memory")
#define CP_WAIT0()     asm volatile("cp.async.wait_group 0;" ::: "memory")

__device__ __forceinline__ void ldsm_x4(uint32_t* r, uint32_t addr) {
    asm volatile("ldmatrix.sync.aligned.m8n8.x4.shared.b16 {%0,%1,%2,%3}, [%4];"
                 : "=r"(r[0]), "=r"(r[1]), "=r"(r[2]), "=r"(r[3]) : "r"(addr));
}
__device__ __forceinline__ void mma16816(float* c, const uint32_t* a, const uint32_t* b) {
    asm volatile("mma.sync.aligned.m16n8k16.row.col.f32.f16.f16.f32 "
                 "{%0,%1,%2,%3}, {%4,%5,%6,%7}, {%8,%9}, {%0,%1,%2,%3};"
                 : "+f"(c[0]), "+f"(c[1]), "+f"(c[2]), "+f"(c[3])
                 : "r"(a[0]), "r"(a[1]), "r"(a[2]), "r"(a[3]), "r"(b[0]), "r"(b[1]));
}

// ============ generic warp-mma GEMM with split-pass K slices =====================
#define STG_BYTES 20480
#define SB_OFF    10240

// MODE 4: out-GEMM, 1 pass (W single, y single). ldK=128 both, nchunks=4.
// MODE 5: merged projections. theta/phi: 3 passes (nch=24); g: 2 passes (nch=16).
template <int MODE>
__global__ __launch_bounds__(256) void mma_gemm(
    const __half* __restrict__ A, const __half* __restrict__ B,
    size_t sAb, size_t sBb,
    float* OF, size_t sOb, int ldO,
    const float* __restrict__ p0, const float* __restrict__ p1,
    const float* __restrict__ p2, const float* __restrict__ p3,
    const float* __restrict__ p4, const float* __restrict__ p5)
{
    constexpr int ldKA = (MODE == 5) ? 512 : 128;
    constexpr int ldKB = (MODE == 5) ? 512 : 128;

    __shared__ __align__(16) char sm[2 * STG_BYTES];
    const uint32_t smb = smem_u32(sm);
    const int tid = threadIdx.x;
    const int wid = tid >> 5, lid = tid & 31;
    const int b = (MODE == 5) ? (blockIdx.z & 7) : blockIdx.z;
    const int which = (MODE == 5) ? (blockIdx.z >> 3) : 0;
    const int nch = (MODE == 5) ? ((which == 2) ? 16 : 24) : 4;
    const int row0 = blockIdx.y * 128, col0 = blockIdx.x * 128;
    const int m_base = (wid & 1) * 64;
    const int n_base = (wid >> 1) * 32;

    const __half* At = A + sAb * b + (size_t)row0 * ldKA;
    const __half* Bt = B + sBb * (size_t)((MODE == 5) ? which : b) + (size_t)col0 * ldKB;

    const int r0i = tid >> 2, s0 = (tid & 3);
    const int r1i = (tid + 256) >> 2;
    const uint32_t d0 = (uint32_t)(r0i * 80 + s0 * 16);
    const uint32_t d1 = (uint32_t)(r1i * 80 + s0 * 16);
    const uint32_t aOff = (uint32_t)((m_base + (lid & 15)) * 80 + (lid >> 4) * 16);
    // x4 B fragment base: lanes 0-15 -> rows n..n+7 (k halves), 16-31 -> rows n+8..n+15
    const uint32_t bOff4 = (uint32_t)((n_base + (lid & 7) + ((lid >> 4) << 3)) * 80
                                      + ((lid >> 3) & 1) * 16);

    float acc[4][4][4] = {};

    auto issue = [&](int ch) {
        int aK, bK;
        if (MODE == 5) {
            const int p = ch / 8, kk = ch - p * 8;
            aK = (p == 1 ? 256 : 0) + kk * 32;
            bK = (p == 2 ? 256 : 0) + kk * 32;
        } else {
            aK = ch * 32;
            bK = ch * 32;
        }
        const uint32_t sa = smb + (uint32_t)(ch & 1) * STG_BYTES;
        const uint32_t sb2 = sa + SB_OFF;
        const __half* ga = At + aK;
        const __half* gb = Bt + bK;
        CP16(sa + d0, ga + (size_t)r0i * ldKA + s0 * 8);
        CP16(sa + d1, ga + (size_t)r1i * ldKA + s0 * 8);
        CP16(sb2 + d0, gb + (size_t)r0i * ldKB + s0 * 8);
        CP16(sb2 + d1, gb + (size_t)r1i * ldKB + s0 * 8);
    };

    issue(0);
    CP_COMMIT();
    for (int ch = 0; ch < nch; ++ch) {
        if (ch + 1 < nch) { issue(ch + 1); CP_COMMIT(); CP_WAIT1(); }
        else CP_WAIT0();
        __syncthreads();
        const uint32_t sa = smb + (uint32_t)(ch & 1) * STG_BYTES;
        const uint32_t sb2 = sa + SB_OFF;
#pragma unroll
        for (int ks = 0; ks < 2; ++ks) {
            uint32_t afr[4][4], b4r[2][4];
#pragma unroll
            for (int mi = 0; mi < 4; ++mi) ldsm_x4(afr[mi], sa + aOff + mi * 1280 + ks * 32);
            ldsm_x4(b4r[0], sb2 + bOff4 + ks * 32);           // ni 0,1
            ldsm_x4(b4r[1], sb2 + bOff4 + 1280 + ks * 32);    // ni 2,3 (16 rows * 80)
#pragma unroll
            for (int mi = 0; mi < 4; ++mi)
#pragma unroll
                for (int ni = 0; ni < 4; ++ni)
                    mma16816(acc[mi][ni], afr[mi], &b4r[ni >> 1][(ni & 1) * 2]);
        }
        __syncthreads();
    }

    const int rl = lid >> 2;
    const int cl = 2 * (lid & 3);

    if constexpr (MODE == 4) {
        float* Ob = OF + sOb * b;
        const float* Xb = p5 + sOb * b;
#pragma unroll
        for (int mi = 0; mi < 4; ++mi)
#pragma unroll
            for (int half = 0; half < 2; ++half) {
                const int c = row0 + m_base + mi * 16 + rl + half * 8;
                const float inv = p1[c] * rsqrtf(p4[c] + BN_EPS);
                const float sh = (p0[c] - p3[c]) * inv + p2[c];
#pragma unroll
                for (int ni = 0; ni < 4; ++ni) {
                    const int cg = col0 + n_base + ni * 8 + cl;
                    float2 xv = *(const float2*)(Xb + (size_t)c * ldO + cg);
                    *(float2*)(Ob + (size_t)c * ldO + cg) = make_float2(
                        acc[mi][ni][2 * half + 0] * inv + sh + xv.x,
                        acc[mi][ni][2 * half + 1] * inv + sh + xv.y);
                }
            }
    } else { // MODE 5
        if (which == 0) {
            __half* Ob = d_th2 + (size_t)b * NPIX * (2 * CI);
#pragma unroll
            for (int mi = 0; mi < 4; ++mi)
#pragma unroll
                for (int ni = 0; ni < 4; ++ni) {
                    const int cg = col0 + n_base + ni * 8 + cl;
#pragma unroll
                    for (int half = 0; half < 2; ++half) {
                        float v0 = acc[mi][ni][2 * half + 0] + p0[cg];
                        float v1 = acc[mi][ni][2 * half + 1] + p0[cg + 1];
                        __half h0 = __float2half_rn(v0);
                        __half h1 = __float2half_rn(v1);
                        __half l0 = __float2half_rn(v0 - __half2float(h0));
                        __half l1 = __float2half_rn(v1 - __half2float(h1));
                        const int rg = row0 + m_base + mi * 16 + rl + half * 8;
                        __half* pr = Ob + (size_t)rg * (2 * CI) + cg;
                        *(uint32_t*)(pr)      = pack_h2(h0, h1);
                        *(uint32_t*)(pr + CI) = pack_h2(l0, l1);
                    }
                }
        } else {
            // Fused 2x2 maxpool epilogue (windows are tile-local).
            float (*stage)[33] = (float(*)[33])sm;
            const float* bias = (which == 1) ? p1 : p2;
            const int t_band = blockIdx.y;
#pragma unroll 1
            for (int cg2 = 0; cg2 < 4; ++cg2) {
                __syncthreads();
                if ((wid >> 1) == cg2) {
#pragma unroll
                    for (int mi = 0; mi < 4; ++mi)
#pragma unroll
                        for (int ni = 0; ni < 4; ++ni) {
                            const int r = m_base + mi * 16 + rl;
                            const int c = ni * 8 + cl;
                            stage[r][c]     = acc[mi][ni][0];
                            stage[r][c + 1] = acc[mi][ni][1];
                            stage[r + 8][c]     = acc[mi][ni][2];
                            stage[r + 8][c + 1] = acc[mi][ni][3];
                        }
                }
                __syncthreads();
                if (which == 1) {
                    const int c = tid & 31, pw0 = (tid >> 5) * 4;
                    const int ci = cg2 * 32 + c;
#pragma unroll
                    for (int j = 0; j < 4; ++j) {
                        const int pw = pw0 + j;
                        float v = fmaxf(fmaxf(stage[2 * pw][c], stage[2 * pw + 1][c]),
                                        fmaxf(stage[2 * pw + 64][c], stage[2 * pw + 65][c]))
                                  + bias[ci];
                        __half h = __float2half_rn(v);
                        __half l = __float2half_rn(v - __half2float(h));
                        const int m = t_band * 32 + pw;
                        __half* pr = d_phiP2 + ((size_t)b * NPOOL + m) * (2 * CI);
                        pr[ci] = h; pr[CI + ci] = l;
                    }
                } else {
                    const int pw = tid & 31, c0v = (tid >> 5) * 4;
                    const int m = t_band * 32 + pw;
#pragma unroll
                    for (int j = 0; j < 4; ++j) {
                        const int c = c0v + j, ci = cg2 * 32 + c;
                        float v = fmaxf(fmaxf(stage[2 * pw][c], stage[2 * pw + 1][c]),
                                        fmaxf(stage[2 * pw + 64][c], stage[2 * pw + 65][c]))
                                  + bias[ci];
                        d_gPh[((size_t)b * CI + ci) * NPOOL + m] = __float2half_rn(v);
                    }
                }
            }
        }
    }
}

// ============ flash kernel (R12 shape; S 3-pass, Y 1-pass; x4 B fragments) ======
#define FL_PITCH1 144
#define FPP 272
#define FS_A    0
#define FS_B    (FS_A + 2 * 18432)
#define FS_PH   (FS_B + 2 * 18432)
#define FS_GH   (FS_PH + 34816)
#define FS_RED  (FS_GH + 34816)
#define FS_RMAX (FS_RED + 2048)
#define FS_RSUM (FS_RMAX + 512)
#define FS_RSC  (FS_RSUM + 512)
#define FS_RBC  (FS_RSC + 512)
#define FL_SMEM (FS_RBC + 512)              // ~147 KB

__global__ __launch_bounds__(512, 1) void flash_kernel()
{
    extern __shared__ __align__(16) char sm[];
    const uint32_t smb = smem_u32(sm);
    float* red  = (float*)(sm + FS_RED);
    float* rmax = (float*)(sm + FS_RMAX);
    float* rsum = (float*)(sm + FS_RSUM);
    float* rsc  = (float*)(sm + FS_RSC);
    float* rbc  = (float*)(sm + FS_RBC);

    const int tid = threadIdx.x, wid = tid >> 5, lid = tid & 31;
    const int b = blockIdx.y;
    const int n0 = blockIdx.x * 128;
    const int mrow = (wid & 3) * 32;
    const int ncol = (wid >> 2) * 32;
    const int nwg = wid >> 2;
    const int rl = lid >> 2, cl = 2 * (lid & 3);

    const __half* At = d_th2 + (size_t)b * NPIX * 256 + (size_t)n0 * 256;
    const __half* Pt = d_phiP2 + (size_t)b * NPOOL * 256;
    const __half* Gh = d_gPh + (size_t)b * CI * NPOOL;

    if (tid < 128) { rmax[tid] = -1e30f; rsum[tid] = 0.f; }
    __syncthreads();

    const uint32_t a1 = (uint32_t)((mrow + (lid & 15)) * FL_PITCH1 + (lid >> 4) * 16);
    const uint32_t b1x4 = (uint32_t)((ncol + (lid & 7) + ((lid >> 4) << 3)) * FL_PITCH1
                                     + ((lid >> 3) & 1) * 16);
    const uint32_t a2 = (uint32_t)((mrow + (lid & 15)) * FPP + (lid >> 4) * 16);
    const uint32_t b2x4 = (uint32_t)((ncol + (lid & 7) + ((lid >> 4) << 3)) * FPP
                                     + ((lid >> 3) & 1) * 16);

    float accY[2][4][4] = {};

    for (int mt = 0; mt < 8; ++mt) {
        const int m0 = mt * 128;

        { // g tile (hi only), 128ci x 128m
            const uint32_t gh = smb + FS_GH;
#pragma unroll
            for (int t = 0; t < 4; ++t) {
                int j = tid + 512 * t;
                int row = j >> 4, seg = j & 15;
                uint32_t dst = (uint32_t)(row * FPP + seg * 16);
                CP16(gh + dst, Gh + (size_t)row * NPOOL + m0 + seg * 8);
            }
            CP_COMMIT();
        }

        auto issue1 = [&](int ch) {
            const int p = ch >> 1, kk = ch & 1;
            const int aK = (p == 1 ? 128 : 0) + kk * 64;
            const int bK = (p == 2 ? 128 : 0) + kk * 64;
            const uint32_t sa = smb + FS_A + (uint32_t)(ch & 1) * 18432;
            const uint32_t sbb = smb + FS_B + (uint32_t)(ch & 1) * 18432;
#pragma unroll
            for (int t = 0; t < 2; ++t) {
                int j = tid + 512 * t;
                int row = j >> 3, seg = j & 7;
                uint32_t dst = (uint32_t)(row * FL_PITCH1 + seg * 16);
                CP16(sa + dst, At + (size_t)row * 256 + aK + seg * 8);
                CP16(sbb + dst, Pt + (size_t)(m0 + row) * 256 + bK + seg * 8);
            }
            CP_COMMIT();
        };

        float accS[2][4][4] = {};
        issue1(0);
        for (int ch = 0; ch < 6; ++ch) {
            if (ch + 1 < 6) { issue1(ch + 1); CP_WAIT1(); }
            else CP_WAIT0();
            __syncthreads();
            const uint32_t sa = smb + FS_A + (uint32_t)(ch & 1) * 18432;
            const uint32_t sbb = smb + FS_B + (uint32_t)(ch & 1) * 18432;
#pragma unroll
            for (int ks = 0; ks < 4; ++ks) {
                uint32_t afr[2][4], b4r[2][4];
#pragma unroll
                for (int mi = 0; mi < 2; ++mi) ldsm_x4(afr[mi], sa + a1 + mi * 16 * FL_PITCH1 + ks * 32);
                ldsm_x4(b4r[0], sbb + b1x4 + ks * 32);                       // ni 0,1
                ldsm_x4(b4r[1], sbb + b1x4 + 16 * FL_PITCH1 + ks * 32);      // ni 2,3
#pragma unroll
                for (int mi = 0; mi < 2; ++mi)
#pragma unroll
                    for (int ni = 0; ni < 4; ++ni)
                        mma16816(accS[mi][ni], afr[mi], &b4r[ni >> 1][(ni & 1) * 2]);
            }
            __syncthreads();
        }

        // ---- online softmax ----
#pragma unroll
        for (int mi = 0; mi < 2; ++mi)
#pragma unroll
            for (int half = 0; half < 2; ++half) {
                float v = -1e30f;
#pragma unroll
                for (int ni = 0; ni < 4; ++ni)
                    v = fmaxf(v, fmaxf(accS[mi][ni][2 * half], accS[mi][ni][2 * half + 1]));
                v = fmaxf(v, __shfl_xor_sync(0xffffffffu, v, 1));
                v = fmaxf(v, __shfl_xor_sync(0xffffffffu, v, 2));
                if ((lid & 3) == 0)
                    red[(mrow + mi * 16 + rl + half * 8) * 4 + nwg] = v;
            }
        __syncthreads();
        if (tid < 128) {
            float mOld = rmax[tid];
            float mNew = fmaxf(fmaxf(red[tid * 4], red[tid * 4 + 1]),
                               fmaxf(red[tid * 4 + 2], red[tid * 4 + 3]));
            mNew = fmaxf(mOld, mNew);
            rbc[tid] = mNew; rsc[tid] = __expf(mOld - mNew); rmax[tid] = mNew;
        }
        __syncthreads();
#pragma unroll
        for (int mi = 0; mi < 2; ++mi)
#pragma unroll
            for (int half = 0; half < 2; ++half) {
                const int r = mrow + mi * 16 + rl + half * 8;
                const float mb = rbc[r];
                const float sc = rsc[r];
                float s = 0.f;
#pragma unroll
                for (int ni = 0; ni < 4; ++ni) {
                    accY[mi][ni][2 * half]     *= sc;
                    accY[mi][ni][2 * half + 1] *= sc;
                    float e0 = __expf(accS[mi][ni][2 * half]     - mb);
                    float e1 = __expf(accS[mi][ni][2 * half + 1] - mb);
                    s += e0 + e1;
                    const uint32_t off = (uint32_t)(r * FPP + (ncol + ni * 8 + cl) * 2);
                    *(uint32_t*)(sm + FS_PH + off) =
                        pack_h2(__float2half_rn(e0), __float2half_rn(e1));
                }
                s += __shfl_xor_sync(0xffffffffu, s, 1);
                s += __shfl_xor_sync(0xffffffffu, s, 2);
                if ((lid & 3) == 0) red[r * 4 + nwg] = s;
            }
        __syncthreads();
        if (tid < 128)
            rsum[tid] = rsum[tid] * rsc[tid] +
                        (red[tid * 4] + red[tid * 4 + 1] + red[tid * 4 + 2] + red[tid * 4 + 3]);

        // ---- phase 2: Y += P * g (1 pass) ----
        {
            const uint32_t ab = smb + FS_PH + a2;
            const uint32_t bb = smb + FS_GH + b2x4;
#pragma unroll
            for (int ks = 0; ks < 8; ++ks) {
                uint32_t afr[2][4], b4r[2][4];
#pragma unroll
                for (int mi = 0; mi < 2; ++mi) ldsm_x4(afr[mi], ab + mi * 16 * FPP + ks * 32);
                ldsm_x4(b4r[0], bb + ks * 32);                 // ni 0,1
                ldsm_x4(b4r[1], bb + 16 * FPP + ks * 32);      // ni 2,3
#pragma unroll
                for (int mi = 0; mi < 2; ++mi)
#pragma unroll
                    for (int ni = 0; ni < 4; ++ni)
                        mma16816(accY[mi][ni], afr[mi], &b4r[ni >> 1][(ni & 1) * 2]);
            }
        }
        __syncthreads();
    }

    // ---- epilogue: normalize, write y single fp16 ----
    __half* Ob = d_y1 + (size_t)b * NPIX * CI + (size_t)n0 * CI;
#pragma unroll
    for (int mi = 0; mi < 2; ++mi)
#pragma unroll
        for (int half = 0; half < 2; ++half) {
            const int r = mrow + mi * 16 + rl + half * 8;
            const float rinv = 1.f / rsum[r];
#pragma unroll
            for (int ni = 0; ni < 4; ++ni) {
                float v0 = accY[mi][ni][2 * half]     * rinv;
                float v1 = accY[mi][ni][2 * half + 1] * rinv;
                *(uint32_t*)(Ob + (size_t)r * CI + (ncol + ni * 8 + cl)) =
                    pack_h2(__float2half_rn(v0), __float2half_rn(v1));
            }
        }
}

// ---------------- x transpose-convert: x[b][c][n] -> x2[b][n][hi|lo] -----------
__global__ __launch_bounds__(256) void conv_x_kernel(const float* __restrict__ x)
{
    __shared__ float t[32][33];
    const int b = blockIdx.z;
    const int c0 = blockIdx.y * 32, n0 = blockIdx.x * 32;
    const int tx = threadIdx.x, ty = threadIdx.y;
    const float* X = x + (size_t)b * CC * NPIX;
#pragma unroll
    for (int i = 0; i < 4; ++i)
        t[ty + 8 * i][tx] = X[(size_t)(c0 + ty + 8 * i) * NPIX + n0 + tx];
    __syncthreads();
    __half* O = d_x2 + (size_t)b * NPIX * (2 * CC);
#pragma unroll
    for (int i = 0; i < 4; ++i) {
        int n = n0 + ty + 8 * i;
        float v = t[tx][ty + 8 * i];
        __half h = __float2half_rn(v);
        __half l = __float2half_rn(v - __half2float(h));
        __half* row = O + (size_t)n * (2 * CC) + c0 + tx;
        row[0] = h; row[CC] = l;
    }
}

// ---------------- merged weight convert (all 4 weights, one launch) -------------
__global__ void conv_w_all(const float* __restrict__ th_w, const float* __restrict__ ph_w,
                           const float* __restrict__ g_w, const float* __restrict__ W_w)
{
    const int which = blockIdx.y;
    int idx = blockIdx.x * 256 + threadIdx.x;
    if (idx >= CI * CC) return;

    if (which == 3) {
        d_Ww1[idx] = __float2half_rn(W_w[idx]);
        return;
    }
    const float* src = which == 0 ? th_w : which == 1 ? ph_w : g_w;
    __half* dst = d_w2all + (size_t)which * CI * (2 * CC);
    int r = idx / CC, k = idx - r * CC;
    float v = src[idx];
    __half h = __float2half_rn(v);
    __half l = __float2half_rn(v - __half2float(h));
    __half* row = dst + (size_t)r * 2 * CC;
    row[k] = h;
    row[CC + k] = l;
}

// ---------------- launch ----------------------------------------------------------
template <typename T>
static T* sym_addr(const void* sym)
{
    void* p = nullptr;
    cudaGetSymbolAddress(&p, sym);
    return (T*)p;
}

extern "C" void kernel_launch(void* const* d_in, const int* in_sizes, int n_in,
                              void* d_out, int out_size)
{
    const float* x    = (const float*)d_in[0];
    const float* g_w  = (const float*)d_in[1];
    const float* g_b  = (const float*)d_in[2];
    const float* th_w = (const float*)d_in[3];
    const float* th_b = (const float*)d_in[4];
    const float* ph_w = (const float*)d_in[5];
    const float* ph_b = (const float*)d_in[6];
    const float* W_w  = (const float*)d_in[7];
    const float* W_b  = (const float*)d_in[8];
    const float* gam  = (const float*)d_in[9];
    const float* bet  = (const float*)d_in[10];
    const float* mea  = (const float*)d_in[11];
    const float* var  = (const float*)d_in[12];
    float* out = (float*)d_out;

    __half* x2    = sym_addr<__half>(d_x2);
    __half* w2all = sym_addr<__half>(d_w2all);
    __half* Ww1   = sym_addr<__half>(d_Ww1);
    __half* y1    = sym_addr<__half>(d_y1);

    cudaFuncSetAttribute(flash_kernel, cudaFuncAttributeMaxDynamicSharedMemorySize, FL_SMEM);

    conv_x_kernel<<<dim3(NPIX / 32, CC / 32, BB), dim3(32, 8)>>>(x);
    conv_w_all<<<dim3((CI * CC + 255) / 256, 4), 256>>>(th_w, ph_w, g_w, W_w);

    // merged projections with fused pool for phi/g: z = which*8 + b
    mma_gemm<5><<<dim3(1, 32, 24), 256>>>(
        x2, w2all, (size_t)NPIX * 512, (size_t)CI * 512,
        nullptr, 0, 0, th_b, ph_b, g_b, nullptr, nullptr, nullptr);

    flash_kernel<<<dim3(NPIX / 128, BB), 512, FL_SMEM>>>();

    // out GEMM: A=Ww1 single [c][ci], B=y1 single [n][ci], 1 pass
    mma_gemm<4><<<dim3(NPIX / 128, CC / 128, BB), 256>>>(
        Ww1, y1, 0, (size_t)NPIX * 128,
        out, (size_t)CC * NPIX, NPIX, W_b, gam, bet, mea, var, x);
}

// round 16
// speedup vs baseline: 1.0941x; 1.0189x over previous
#include <cuda_runtime.h>
#include <cuda_fp16.h>
#include <math.h>
#include <stdint.h>

#define BB 8
#define CC 256
#define CI 128
#define NPIX 4096
#define NPOOL 1024
#define WD 64
#define BN_EPS 1e-5f

// ---------------- scratch (__device__ globals, no allocations) ----------------
__device__ __align__(16) __half d_x2  [(size_t)BB * NPIX * (2 * CC)];   // [b][n][hi|lo]
__device__ __align__(16) __half d_w2all[(size_t)3 * CI * 2 * CC];       // theta|phi|g: [ci][hi|lo]
__device__ __align__(16) __half d_Ww1 [(size_t)CC * CI];                // [c][ci] single fp16
__device__ __align__(16) __half d_th2 [(size_t)BB * NPIX * (2 * CI)];   // [b][n][hi|lo]
__device__ __align__(16) __half d_phiP2[(size_t)BB * NPOOL * (2 * CI)]; // [b][m][hi|lo]
__device__ __align__(16) __half d_gPh [(size_t)BB * CI * NPOOL];        // [b][ci][m] single fp16
__device__ __align__(16) __half d_y1  [(size_t)BB * NPIX * CI];         // [b][n][ci] single fp16

// ---------------- helpers -------------------------------------------------------
__device__ __forceinline__ uint32_t smem_u32(const void* p) {
    uint32_t a;
    asm("{ .reg .u64 t; cvta.to.shared.u64 t, %1; cvt.u32.u64 %0, t; }" : "=r"(a) : "l"(p));
    return a;
}
__device__ __forceinline__ uint32_t pack_h2(__half a, __half b) {
    __half2 h(a, b);
    return *(uint32_t*)&h;
}
#define CP16(dst, src) asm volatile("cp.async.ca.shared.global [%0], [%1], 16;" :: "r"(dst), "l"(src))
#define CP_COMMIT()    asm volatile("cp.async.commit_group;" ::: "memory")
#define CP_WAIT1()     asm volatile("cp.async.wait_group 1;" ::: "memory")
#define CP_WAIT0()     asm volatile("cp.async.wait_group 0;" ::: "memory")

__device__ __forceinline__ void ldsm_x4(uint32_t* r, uint32_t addr) {
    asm volatile("ldmatrix.sync.aligned.m8n8.x4.shared.b16 {%0,%1,%2,%3}, [%4];"
                 : "=r"(r[0]), "=r"(r[1]), "=r"(r[2]), "=r"(r[3]) : "r"(addr));
}
__device__ __forceinline__ void mma16816(float* c, const uint32_t* a, const uint32_t* b) {
    asm volatile("mma.sync.aligned.m16n8k16.row.col.f32.f16.f16.f32 "
                 "{%0,%1,%2,%3}, {%4,%5,%6,%7}, {%8,%9}, {%0,%1,%2,%3};"
                 : "+f"(c[0]), "+f"(c[1]), "+f"(c[2]), "+f"(c[3])
                 : "r"(a[0]), "r"(a[1]), "r"(a[2]), "r"(a[3]), "r"(b[0]), "r"(b[1]));
}

// ============ generic warp-mma GEMM, 3-deep cp.async pipeline ====================
#define STG_BYTES 20480
#define SB_OFF    10240

// MODE 4: out-GEMM, 1 pass (W single, y single). ldK=128 both, nchunks=4.
// MODE 5: merged projections. theta/phi: 3 passes (nch=24); g: 2 passes (nch=16).
template <int MODE>
__global__ __launch_bounds__(256) void mma_gemm(
    const __half* __restrict__ A, const __half* __restrict__ B,
    size_t sAb, size_t sBb,
    float* OF, size_t sOb, int ldO,
    const float* __restrict__ p0, const float* __restrict__ p1,
    const float* __restrict__ p2, const float* __restrict__ p3,
    const float* __restrict__ p4, const float* __restrict__ p5)
{
    constexpr int ldKA = (MODE == 5) ? 512 : 128;
    constexpr int ldKB = (MODE == 5) ? 512 : 128;

    __shared__ __align__(16) char sm[3 * STG_BYTES];
    const uint32_t smb = smem_u32(sm);
    const int tid = threadIdx.x;
    const int wid = tid >> 5, lid = tid & 31;
    const int b = (MODE == 5) ? (blockIdx.z & 7) : blockIdx.z;
    const int which = (MODE == 5) ? (blockIdx.z >> 3) : 0;
    const int nch = (MODE == 5) ? ((which == 2) ? 16 : 24) : 4;
    const int row0 = blockIdx.y * 128, col0 = blockIdx.x * 128;
    const int m_base = (wid & 1) * 64;
    const int n_base = (wid >> 1) * 32;

    const __half* At = A + sAb * b + (size_t)row0 * ldKA;
    const __half* Bt = B + sBb * (size_t)((MODE == 5) ? which : b) + (size_t)col0 * ldKB;

    const int r0i = tid >> 2, s0 = (tid & 3);
    const int r1i = (tid + 256) >> 2;
    const uint32_t d0 = (uint32_t)(r0i * 80 + s0 * 16);
    const uint32_t d1 = (uint32_t)(r1i * 80 + s0 * 16);
    const uint32_t aOff = (uint32_t)((m_base + (lid & 15)) * 80 + (lid >> 4) * 16);
    const uint32_t bOff4 = (uint32_t)((n_base + (lid & 7) + ((lid >> 4) << 3)) * 80
                                      + ((lid >> 3) & 1) * 16);

    float acc[4][4][4] = {};

    auto issue = [&](int ch) {
        int aK, bK;
        if (MODE == 5) {
            const int p = ch / 8, kk = ch - p * 8;
            aK = (p == 1 ? 256 : 0) + kk * 32;
            bK = (p == 2 ? 256 : 0) + kk * 32;
        } else {
            aK = ch * 32;
            bK = ch * 32;
        }
        const uint32_t sa = smb + (uint32_t)(ch % 3) * STG_BYTES;
        const uint32_t sb2 = sa + SB_OFF;
        const __half* ga = At + aK;
        const __half* gb = Bt + bK;
        CP16(sa + d0, ga + (size_t)r0i * ldKA + s0 * 8);
        CP16(sa + d1, ga + (size_t)r1i * ldKA + s0 * 8);
        CP16(sb2 + d0, gb + (size_t)r0i * ldKB + s0 * 8);
        CP16(sb2 + d1, gb + (size_t)r1i * ldKB + s0 * 8);
    };

    issue(0); CP_COMMIT();
    issue(1); CP_COMMIT();
    for (int ch = 0; ch < nch; ++ch) {
        if (ch + 1 < nch) CP_WAIT1(); else CP_WAIT0();
        __syncthreads();
        if (ch + 2 < nch) { issue(ch + 2); CP_COMMIT(); }
        const uint32_t sa = smb + (uint32_t)(ch % 3) * STG_BYTES;
        const uint32_t sb2 = sa + SB_OFF;
#pragma unroll
        for (int ks = 0; ks < 2; ++ks) {
            uint32_t afr[4][4], b4r[2][4];
#pragma unroll
            for (int mi = 0; mi < 4; ++mi) ldsm_x4(afr[mi], sa + aOff + mi * 1280 + ks * 32);
            ldsm_x4(b4r[0], sb2 + bOff4 + ks * 32);           // ni 0,1
            ldsm_x4(b4r[1], sb2 + bOff4 + 1280 + ks * 32);    // ni 2,3
#pragma unroll
            for (int mi = 0; mi < 4; ++mi)
#pragma unroll
                for (int ni = 0; ni < 4; ++ni)
                    mma16816(acc[mi][ni], afr[mi], &b4r[ni >> 1][(ni & 1) * 2]);
        }
    }

    const int rl = lid >> 2;
    const int cl = 2 * (lid & 3);

    if constexpr (MODE == 4) {
        float* Ob = OF + sOb * b;
        const float* Xb = p5 + sOb * b;
#pragma unroll
        for (int mi = 0; mi < 4; ++mi)
#pragma unroll
            for (int half = 0; half < 2; ++half) {
                const int c = row0 + m_base + mi * 16 + rl + half * 8;
                const float inv = p1[c] * rsqrtf(p4[c] + BN_EPS);
                const float sh = (p0[c] - p3[c]) * inv + p2[c];
#pragma unroll
                for (int ni = 0; ni < 4; ++ni) {
                    const int cg = col0 + n_base + ni * 8 + cl;
                    float2 xv = *(const float2*)(Xb + (size_t)c * ldO + cg);
                    *(float2*)(Ob + (size_t)c * ldO + cg) = make_float2(
                        acc[mi][ni][2 * half + 0] * inv + sh + xv.x,
                        acc[mi][ni][2 * half + 1] * inv + sh + xv.y);
                }
            }
    } else { // MODE 5
        if (which == 0) {
            __half* Ob = d_th2 + (size_t)b * NPIX * (2 * CI);
#pragma unroll
            for (int mi = 0; mi < 4; ++mi)
#pragma unroll
                for (int ni = 0; ni < 4; ++ni) {
                    const int cg = col0 + n_base + ni * 8 + cl;
#pragma unroll
                    for (int half = 0; half < 2; ++half) {
                        float v0 = acc[mi][ni][2 * half + 0] + p0[cg];
                        float v1 = acc[mi][ni][2 * half + 1] + p0[cg + 1];
                        __half h0 = __float2half_rn(v0);
                        __half h1 = __float2half_rn(v1);
                        __half l0 = __float2half_rn(v0 - __half2float(h0));
                        __half l1 = __float2half_rn(v1 - __half2float(h1));
                        const int rg = row0 + m_base + mi * 16 + rl + half * 8;
                        __half* pr = Ob + (size_t)rg * (2 * CI) + cg;
                        *(uint32_t*)(pr)      = pack_h2(h0, h1);
                        *(uint32_t*)(pr + CI) = pack_h2(l0, l1);
                    }
                }
        } else {
            // Fused 2x2 maxpool epilogue (windows are tile-local).
            float (*stage)[33] = (float(*)[33])sm;
            const float* bias = (which == 1) ? p1 : p2;
            const int t_band = blockIdx.y;
#pragma unroll 1
            for (int cg2 = 0; cg2 < 4; ++cg2) {
                __syncthreads();
                if ((wid >> 1) == cg2) {
#pragma unroll
                    for (int mi = 0; mi < 4; ++mi)
#pragma unroll
                        for (int ni = 0; ni < 4; ++ni) {
                            const int r = m_base + mi * 16 + rl;
                            const int c = ni * 8 + cl;
                            stage[r][c]     = acc[mi][ni][0];
                            stage[r][c + 1] = acc[mi][ni][1];
                            stage[r + 8][c]     = acc[mi][ni][2];
                            stage[r + 8][c + 1] = acc[mi][ni][3];
                        }
                }
                __syncthreads();
                if (which == 1) {
                    const int c = tid & 31, pw0 = (tid >> 5) * 4;
                    const int ci = cg2 * 32 + c;
#pragma unroll
                    for (int j = 0; j < 4; ++j) {
                        const int pw = pw0 + j;
                        float v = fmaxf(fmaxf(stage[2 * pw][c], stage[2 * pw + 1][c]),
                                        fmaxf(stage[2 * pw + 64][c], stage[2 * pw + 65][c]))
                                  + bias[ci];
                        __half h = __float2half_rn(v);
                        __half l = __float2half_rn(v - __half2float(h));
                        const int m = t_band * 32 + pw;
                        __half* pr = d_phiP2 + ((size_t)b * NPOOL + m) * (2 * CI);
                        pr[ci] = h; pr[CI + ci] = l;
                    }
                } else {
                    const int pw = tid & 31, c0v = (tid >> 5) * 4;
                    const int m = t_band * 32 + pw;
#pragma unroll
                    for (int j = 0; j < 4; ++j) {
                        const int c = c0v + j, ci = cg2 * 32 + c;
                        float v = fmaxf(fmaxf(stage[2 * pw][c], stage[2 * pw + 1][c]),
                                        fmaxf(stage[2 * pw + 64][c], stage[2 * pw + 65][c]))
                                  + bias[ci];
                        d_gPh[((size_t)b * CI + ci) * NPOOL + m] = __float2half_rn(v);
                    }
                }
            }
        }
    }
}

// ============ flash kernel (R15 + 3-deep S-phase pipeline) =======================
#define FL_PITCH1 144
#define FPP 272
#define FS_A    0
#define FS_B    (FS_A + 3 * 18432)          // 55296
#define FS_PH   (FS_B + 3 * 18432)          // 110592
#define FS_GH   (FS_PH + 34816)             // 145408
#define FS_RED  (FS_GH + 34816)             // 180224
#define FS_RMAX (FS_RED + 2048)
#define FS_RSUM (FS_RMAX + 512)
#define FS_RSC  (FS_RSUM + 512)
#define FS_RBC  (FS_RSC + 512)
#define FL_SMEM (FS_RBC + 512)              // ~184 KB

__global__ __launch_bounds__(512, 1) void flash_kernel()
{
    extern __shared__ __align__(16) char sm[];
    const uint32_t smb = smem_u32(sm);
    float* red  = (float*)(sm + FS_RED);
    float* rmax = (float*)(sm + FS_RMAX);
    float* rsum = (float*)(sm + FS_RSUM);
    float* rsc  = (float*)(sm + FS_RSC);
    float* rbc  = (float*)(sm + FS_RBC);

    const int tid = threadIdx.x, wid = tid >> 5, lid = tid & 31;
    const int b = blockIdx.y;
    const int n0 = blockIdx.x * 128;
    const int mrow = (wid & 3) * 32;
    const int ncol = (wid >> 2) * 32;
    const int nwg = wid >> 2;
    const int rl = lid >> 2, cl = 2 * (lid & 3);

    const __half* At = d_th2 + (size_t)b * NPIX * 256 + (size_t)n0 * 256;
    const __half* Pt = d_phiP2 + (size_t)b * NPOOL * 256;
    const __half* Gh = d_gPh + (size_t)b * CI * NPOOL;

    if (tid < 128) { rmax[tid] = -1e30f; rsum[tid] = 0.f; }
    __syncthreads();

    const uint32_t a1 = (uint32_t)((mrow + (lid & 15)) * FL_PITCH1 + (lid >> 4) * 16);
    const uint32_t b1x4 = (uint32_t)((ncol + (lid & 7) + ((lid >> 4) << 3)) * FL_PITCH1
                                     + ((lid >> 3) & 1) * 16);
    const uint32_t a2 = (uint32_t)((mrow + (lid & 15)) * FPP + (lid >> 4) * 16);
    const uint32_t b2x4 = (uint32_t)((ncol + (lid & 7) + ((lid >> 4) << 3)) * FPP
                                     + ((lid >> 3) & 1) * 16);

    float accY[2][4][4] = {};

    for (int mt = 0; mt < 8; ++mt) {
        const int m0 = mt * 128;

        { // g tile (hi only), 128ci x 128m — group G
            const uint32_t gh = smb + FS_GH;
#pragma unroll
            for (int t = 0; t < 4; ++t) {
                int j = tid + 512 * t;
                int row = j >> 4, seg = j & 15;
                uint32_t dst = (uint32_t)(row * FPP + seg * 16);
                CP16(gh + dst, Gh + (size_t)row * NPOOL + m0 + seg * 8);
            }
            CP_COMMIT();
        }

        auto issue1 = [&](int ch) {
            const int p = ch >> 1, kk = ch & 1;
            const int aK = (p == 1 ? 128 : 0) + kk * 64;
            const int bK = (p == 2 ? 128 : 0) + kk * 64;
            const uint32_t sa = smb + FS_A + (uint32_t)(ch % 3) * 18432;
            const uint32_t sbb = smb + FS_B + (uint32_t)(ch % 3) * 18432;
#pragma unroll
            for (int t = 0; t < 2; ++t) {
                int j = tid + 512 * t;
                int row = j >> 3, seg = j & 7;
                uint32_t dst = (uint32_t)(row * FL_PITCH1 + seg * 16);
                CP16(sa + dst, At + (size_t)row * 256 + aK + seg * 8);
                CP16(sbb + dst, Pt + (size_t)(m0 + row) * 256 + bK + seg * 8);
            }
            CP_COMMIT();
        };

        float accS[2][4][4] = {};
        issue1(0);
        issue1(1);
        for (int ch = 0; ch < 6; ++ch) {
            if (ch + 1 < 6) CP_WAIT1(); else CP_WAIT0();
            __syncthreads();
            if (ch + 2 < 6) issue1(ch + 2);
            const uint32_t sa = smb + FS_A + (uint32_t)(ch % 3) * 18432;
            const uint32_t sbb = smb + FS_B + (uint32_t)(ch % 3) * 18432;
#pragma unroll
            for (int ks = 0; ks < 4; ++ks) {
                uint32_t afr[2][4], b4r[2][4];
#pragma unroll
                for (int mi = 0; mi < 2; ++mi) ldsm_x4(afr[mi], sa + a1 + mi * 16 * FL_PITCH1 + ks * 32);
                ldsm_x4(b4r[0], sbb + b1x4 + ks * 32);                       // ni 0,1
                ldsm_x4(b4r[1], sbb + b1x4 + 16 * FL_PITCH1 + ks * 32);      // ni 2,3
#pragma unroll
                for (int mi = 0; mi < 2; ++mi)
#pragma unroll
                    for (int ni = 0; ni < 4; ++ni)
                        mma16816(accS[mi][ni], afr[mi], &b4r[ni >> 1][(ni & 1) * 2]);
            }
        }

        // ---- online softmax ----
#pragma unroll
        for (int mi = 0; mi < 2; ++mi)
#pragma unroll
            for (int half = 0; half < 2; ++half) {
                float v = -1e30f;
#pragma unroll
                for (int ni = 0; ni < 4; ++ni)
                    v = fmaxf(v, fmaxf(accS[mi][ni][2 * half], accS[mi][ni][2 * half + 1]));
                v = fmaxf(v, __shfl_xor_sync(0xffffffffu, v, 1));
                v = fmaxf(v, __shfl_xor_sync(0xffffffffu, v, 2));
                if ((lid & 3) == 0)
                    red[(mrow + mi * 16 + rl + half * 8) * 4 + nwg] = v;
            }
        __syncthreads();
        if (tid < 128) {
            float mOld = rmax[tid];
            float mNew = fmaxf(fmaxf(red[tid * 4], red[tid * 4 + 1]),
                               fmaxf(red[tid * 4 + 2], red[tid * 4 + 3]));
            mNew = fmaxf(mOld, mNew);
            rbc[tid] = mNew; rsc[tid] = __expf(mOld - mNew); rmax[tid] = mNew;
        }
        __syncthreads();
#pragma unroll
        for (int mi = 0; mi < 2; ++mi)
#pragma unroll
            for (int half = 0; half < 2; ++half) {
                const int r = mrow + mi * 16 + rl + half * 8;
                const float mb = rbc[r];
                const float sc = rsc[r];
                float s = 0.f;
#pragma unroll
                for (int ni = 0; ni < 4; ++ni) {
                    accY[mi][ni][2 * half]     *= sc;
                    accY[mi][ni][2 * half + 1] *= sc;
                    float e0 = __expf(accS[mi][ni][2 * half]     - mb);
                    float e1 = __expf(accS[mi][ni][2 * half + 1] - mb);
                    s += e0 + e1;
                    const uint32_t off = (uint32_t)(r * FPP + (ncol + ni * 8 + cl) * 2);
                    *(uint32_t*)(sm + FS_PH + off) =
                        pack_h2(__float2half_rn(e0), __float2half_rn(e1));
                }
                s += __shfl_xor_sync(0xffffffffu, s, 1);
                s += __shfl_xor_sync(0xffffffffu, s, 2);
                if ((lid & 3) == 0) red[r * 4 + nwg] = s;
            }
        __syncthreads();
        if (tid < 128)
            rsum[tid] = rsum[tid] * rsc[tid] +
                        (red[tid * 4] + red[tid * 4 + 1] + red[tid * 4 + 2] + red[tid * 4 + 3]);

        // ---- phase 2: Y += P * g (1 pass) ----
        {
            const uint32_t ab = smb + FS_PH + a2;
            const uint32_t bb = smb + FS_GH + b2x4;
#pragma unroll
            for (int ks = 0; ks < 8; ++ks) {
                uint32_t afr[2][4], b4r[2][4];
#pragma unroll
                for (int mi = 0; mi < 2; ++mi) ldsm_x4(afr[mi], ab + mi * 16 * FPP + ks * 32);
                ldsm_x4(b4r[0], bb + ks * 32);                 // ni 0,1
                ldsm_x4(b4r[1], bb + 16 * FPP + ks * 32);      // ni 2,3
#pragma unroll
                for (int mi = 0; mi < 2; ++mi)
#pragma unroll
                    for (int ni = 0; ni < 4; ++ni)
                        mma16816(accY[mi][ni], afr[mi], &b4r[ni >> 1][(ni & 1) * 2]);
            }
        }
        __syncthreads();   // protect PH/GH/red before next tile
    }

    // ---- epilogue: normalize, write y single fp16 ----
    __half* Ob = d_y1 + (size_t)b * NPIX * CI + (size_t)n0 * CI;
#pragma unroll
    for (int mi = 0; mi < 2; ++mi)
#pragma unroll
        for (int half = 0; half < 2; ++half) {
            const int r = mrow + mi * 16 + rl + half * 8;
            const float rinv = 1.f / rsum[r];
#pragma unroll
            for (int ni = 0; ni < 4; ++ni) {
                float v0 = accY[mi][ni][2 * half]     * rinv;
                float v1 = accY[mi][ni][2 * half + 1] * rinv;
                *(uint32_t*)(Ob + (size_t)r * CI + (ncol + ni * 8 + cl)) =
                    pack_h2(__float2half_rn(v0), __float2half_rn(v1));
            }
        }
}

// ---------------- x transpose-convert: x[b][c][n] -> x2[b][n][hi|lo] -----------
__global__ __launch_bounds__(256) void conv_x_kernel(const float* __restrict__ x)
{
    __shared__ float t[32][33];
    const int b = blockIdx.z;
    const int c0 = blockIdx.y * 32, n0 = blockIdx.x * 32;
    const int tx = threadIdx.x, ty = threadIdx.y;
    const float* X = x + (size_t)b * CC * NPIX;
#pragma unroll
    for (int i = 0; i < 4; ++i)
        t[ty + 8 * i][tx] = X[(size_t)(c0 + ty + 8 * i) * NPIX + n0 + tx];
    __syncthreads();
    __half* O = d_x2 + (size_t)b * NPIX * (2 * CC);
#pragma unroll
    for (int i = 0; i < 4; ++i) {
        int n = n0 + ty + 8 * i;
        float v = t[tx][ty + 8 * i];
        __half h = __float2half_rn(v);
        __half l = __float2half_rn(v - __half2float(h));
        __half* row = O + (size_t)n * (2 * CC) + c0 + tx;
        row[0] = h; row[CC] = l;
    }
}

// ---------------- merged weight convert (all 4 weights, one launch) -------------
__global__ void conv_w_all(const float* __restrict__ th_w, const float* __restrict__ ph_w,
                           const float* __restrict__ g_w, const float* __restrict__ W_w)
{
    const int which = blockIdx.y;
    int idx = blockIdx.x * 256 + threadIdx.x;
    if (idx >= CI * CC) return;

    if (which == 3) {
        d_Ww1[idx] = __float2half_rn(W_w[idx]);
        return;
    }
    const float* src = which == 0 ? th_w : which == 1 ? ph_w : g_w;
    __half* dst = d_w2all + (size_t)which * CI * (2 * CC);
    int r = idx / CC, k = idx - r * CC;
    float v = src[idx];
    __half h = __float2half_rn(v);
    __half l = __float2half_rn(v - __half2float(h));
    __half* row = dst + (size_t)r * 2 * CC;
    row[k] = h;
    row[CC + k] = l;
}

// ---------------- launch ----------------------------------------------------------
template <typename T>
static T* sym_addr(const void* sym)
{
    void* p = nullptr;
    cudaGetSymbolAddress(&p, sym);
    return (T*)p;
}

extern "C" void kernel_launch(void* const* d_in, const int* in_sizes, int n_in,
                              void* d_out, int out_size)
{
    const float* x    = (const float*)d_in[0];
    const float* g_w  = (const float*)d_in[1];
    const float* g_b  = (const float*)d_in[2];
    const float* th_w = (const float*)d_in[3];
    const float* th_b = (const float*)d_in[4];
    const float* ph_w = (const float*)d_in[5];
    const float* ph_b = (const float*)d_in[6];
    const float* W_w  = (const float*)d_in[7];
    const float* W_b  = (const float*)d_in[8];
    const float* gam  = (const float*)d_in[9];
    const float* bet  = (const float*)d_in[10];
    const float* mea  = (const float*)d_in[11];
    const float* var  = (const float*)d_in[12];
    float* out = (float*)d_out;

    __half* x2    = sym_addr<__half>(d_x2);
    __half* w2all = sym_addr<__half>(d_w2all);
    __half* Ww1   = sym_addr<__half>(d_Ww1);
    __half* y1    = sym_addr<__half>(d_y1);

    cudaFuncSetAttribute(flash_kernel, cudaFuncAttributeMaxDynamicSharedMemorySize, FL_SMEM);

    conv_x_kernel<<<dim3(NPIX / 32, CC / 32, BB), dim3(32, 8)>>>(x);
    conv_w_all<<<dim3((CI * CC + 255) / 256, 4), 256>>>(th_w, ph_w, g_w, W_w);

    // merged projections with fused pool for phi/g: z = which*8 + b
    mma_gemm<5><<<dim3(1, 32, 24), 256>>>(
        x2, w2all, (size_t)NPIX * 512, (size_t)CI * 512,
        nullptr, 0, 0, th_b, ph_b, g_b, nullptr, nullptr, nullptr);

    flash_kernel<<<dim3(NPIX / 128, BB), 512, FL_SMEM>>>();

    // out GEMM: A=Ww1 single [c][ci], B=y1 single [n][ci], 1 pass
    mma_gemm<4><<<dim3(NPIX / 128, CC / 128, BB), 256>>>(
        Ww1, y1, 0, (size_t)NPIX * 128,
        out, (size_t)CC * NPIX, NPIX, W_b, gam, bet, mea, var, x);
}

// round 17
// speedup vs baseline: 1.1116x; 1.0160x over previous
#include <cuda_runtime.h>
#include <cuda_fp16.h>
#include <math.h>
#include <stdint.h>

#define BB 8
#define CC 256
#define CI 128
#define NPIX 4096
#define NPOOL 1024
#define WD 64
#define BN_EPS 1e-5f

// ---------------- scratch (__device__ globals, no allocations) ----------------
__device__ __align__(16) __half d_x2  [(size_t)BB * NPIX * (2 * CC)];   // [b][n][hi|lo]
__device__ __align__(16) __half d_w2all[(size_t)3 * CI * 2 * CC];       // theta|phi|g: [ci][hi|lo]
__device__ __align__(16) __half d_Ww1 [(size_t)CC * CI];                // [c][ci] single fp16
__device__ __align__(16) __half d_th2 [(size_t)BB * NPIX * (2 * CI)];   // [b][n][hi|lo]
__device__ __align__(16) __half d_phiP2[(size_t)BB * NPOOL * (2 * CI)]; // [b][m][hi|lo]
__device__ __align__(16) __half d_gPh [(size_t)BB * CI * NPOOL];        // [b][ci][m] single fp16
__device__ __align__(16) __half d_y1  [(size_t)BB * NPIX * CI];         // [b][n][ci] single fp16

// ---------------- helpers -------------------------------------------------------
__device__ __forceinline__ uint32_t smem_u32(const void* p) {
    uint32_t a;
    asm("{ .reg .u64 t; cvta.to.shared.u64 t, %1; cvt.u32.u64 %0, t; }" : "=r"(a) : "l"(p));
    return a;
}
__device__ __forceinline__ uint32_t pack_h2(__half a, __half b) {
    __half2 h(a, b);
    return *(uint32_t*)&h;
}
#define CP16(dst, src) asm volatile("cp.async.ca.shared.global [%0], [%1], 16;" :: "r"(dst), "l"(src))
#define CP_COMMIT()    asm volatile("cp.async.commit_group;" ::: "memory")
#define CP_WAIT1()     asm volatile("cp.async.wait_group 1;" ::: "memory")
#define CP_WAIT0()     asm volatile("cp.async.wait_group 0;" ::: "memory")

__device__ __forceinline__ void ldsm_x4(uint32_t* r, uint32_t addr) {
    asm volatile("ldmatrix.sync.aligned.m8n8.x4.shared.b16 {%0,%1,%2,%3}, [%4];"
                 : "=r"(r[0]), "=r"(r[1]), "=r"(r[2]), "=r"(r[3]) : "r"(addr));
}
__device__ __forceinline__ void mma16816(float* c, const uint32_t* a, const uint32_t* b) {
    asm volatile("mma.sync.aligned.m16n8k16.row.col.f32.f16.f16.f32 "
                 "{%0,%1,%2,%3}, {%4,%5,%6,%7}, {%8,%9}, {%0,%1,%2,%3};"
                 : "+f"(c[0]), "+f"(c[1]), "+f"(c[2]), "+f"(c[3])
                 : "r"(a[0]), "r"(a[1]), "r"(a[2]), "r"(a[3]), "r"(b[0]), "r"(b[1]));
}

// ============ generic warp-mma GEMM, 3-deep cp.async pipeline ====================
#define STG_BYTES 20480
#define SB_OFF    10240

// MODE 4: out-GEMM, 1 pass (W single, y single). ldK=128 both, nchunks=4.
// MODE 5: merged projections. theta/phi: 3 passes (nch=24); g: 2 passes (nch=16).
template <int MODE>
__global__ __launch_bounds__(256) void mma_gemm(
    const __half* __restrict__ A, const __half* __restrict__ B,
    size_t sAb, size_t sBb,
    float* OF, size_t sOb, int ldO,
    const float* __restrict__ p0, const float* __restrict__ p1,
    const float* __restrict__ p2, const float* __restrict__ p3,
    const float* __restrict__ p4, const float* __restrict__ p5)
{
    constexpr int ldKA = (MODE == 5) ? 512 : 128;
    constexpr int ldKB = (MODE == 5) ? 512 : 128;

    __shared__ __align__(16) char sm[3 * STG_BYTES];
    const uint32_t smb = smem_u32(sm);
    const int tid = threadIdx.x;
    const int wid = tid >> 5, lid = tid & 31;
    const int b = (MODE == 5) ? (blockIdx.z & 7) : blockIdx.z;
    const int which = (MODE == 5) ? (blockIdx.z >> 3) : 0;
    const int nch = (MODE == 5) ? ((which == 2) ? 16 : 24) : 4;
    const int row0 = blockIdx.y * 128, col0 = blockIdx.x * 128;
    const int m_base = (wid & 1) * 64;
    const int n_base = (wid >> 1) * 32;

    const __half* At = A + sAb * b + (size_t)row0 * ldKA;
    const __half* Bt = B + sBb * (size_t)((MODE == 5) ? which : b) + (size_t)col0 * ldKB;

    const int r0i = tid >> 2, s0 = (tid & 3);
    const int r1i = (tid + 256) >> 2;
    const uint32_t d0 = (uint32_t)(r0i * 80 + s0 * 16);
    const uint32_t d1 = (uint32_t)(r1i * 80 + s0 * 16);
    const uint32_t aOff = (uint32_t)((m_base + (lid & 15)) * 80 + (lid >> 4) * 16);
    const uint32_t bOff4 = (uint32_t)((n_base + (lid & 7) + ((lid >> 4) << 3)) * 80
                                      + ((lid >> 3) & 1) * 16);

    float acc[4][4][4] = {};

    auto issue = [&](int ch) {
        int aK, bK;
        if (MODE == 5) {
            const int p = ch / 8, kk = ch - p * 8;
            aK = (p == 1 ? 256 : 0) + kk * 32;
            bK = (p == 2 ? 256 : 0) + kk * 32;
        } else {
            aK = ch * 32;
            bK = ch * 32;
        }
        const uint32_t sa = smb + (uint32_t)(ch % 3) * STG_BYTES;
        const uint32_t sb2 = sa + SB_OFF;
        const __half* ga = At + aK;
        const __half* gb = Bt + bK;
        CP16(sa + d0, ga + (size_t)r0i * ldKA + s0 * 8);
        CP16(sa + d1, ga + (size_t)r1i * ldKA + s0 * 8);
        CP16(sb2 + d0, gb + (size_t)r0i * ldKB + s0 * 8);
        CP16(sb2 + d1, gb + (size_t)r1i * ldKB + s0 * 8);
    };

    issue(0); CP_COMMIT();
    issue(1); CP_COMMIT();
    for (int ch = 0; ch < nch; ++ch) {
        if (ch + 1 < nch) CP_WAIT1(); else CP_WAIT0();
        __syncthreads();
        if (ch + 2 < nch) { issue(ch + 2); CP_COMMIT(); }
        const uint32_t sa = smb + (uint32_t)(ch % 3) * STG_BYTES;
        const uint32_t sb2 = sa + SB_OFF;
#pragma unroll
        for (int ks = 0; ks < 2; ++ks) {
            uint32_t afr[4][4], b4r[2][4];
#pragma unroll
            for (int mi = 0; mi < 4; ++mi) ldsm_x4(afr[mi], sa + aOff + mi * 1280 + ks * 32);
            ldsm_x4(b4r[0], sb2 + bOff4 + ks * 32);           // ni 0,1
            ldsm_x4(b4r[1], sb2 + bOff4 + 1280 + ks * 32);    // ni 2,3
#pragma unroll
            for (int mi = 0; mi < 4; ++mi)
#pragma unroll
                for (int ni = 0; ni < 4; ++ni)
                    mma16816(acc[mi][ni], afr[mi], &b4r[ni >> 1][(ni & 1) * 2]);
        }
    }

    const int rl = lid >> 2;
    const int cl = 2 * (lid & 3);

    if constexpr (MODE == 4) {
        float* Ob = OF + sOb * b;
        const float* Xb = p5 + sOb * b;
#pragma unroll
        for (int mi = 0; mi < 4; ++mi)
#pragma unroll
            for (int half = 0; half < 2; ++half) {
                const int c = row0 + m_base + mi * 16 + rl + half * 8;
                const float inv = p1[c] * rsqrtf(p4[c] + BN_EPS);
                const float sh = (p0[c] - p3[c]) * inv + p2[c];
#pragma unroll
                for (int ni = 0; ni < 4; ++ni) {
                    const int cg = col0 + n_base + ni * 8 + cl;
                    float2 xv = *(const float2*)(Xb + (size_t)c * ldO + cg);
                    *(float2*)(Ob + (size_t)c * ldO + cg) = make_float2(
                        acc[mi][ni][2 * half + 0] * inv + sh + xv.x,
                        acc[mi][ni][2 * half + 1] * inv + sh + xv.y);
                }
            }
    } else { // MODE 5
        if (which == 0) {
            __half* Ob = d_th2 + (size_t)b * NPIX * (2 * CI);
#pragma unroll
            for (int mi = 0; mi < 4; ++mi)
#pragma unroll
                for (int ni = 0; ni < 4; ++ni) {
                    const int cg = col0 + n_base + ni * 8 + cl;
#pragma unroll
                    for (int half = 0; half < 2; ++half) {
                        float v0 = acc[mi][ni][2 * half + 0] + p0[cg];
                        float v1 = acc[mi][ni][2 * half + 1] + p0[cg + 1];
                        __half h0 = __float2half_rn(v0);
                        __half h1 = __float2half_rn(v1);
                        __half l0 = __float2half_rn(v0 - __half2float(h0));
                        __half l1 = __float2half_rn(v1 - __half2float(h1));
                        const int rg = row0 + m_base + mi * 16 + rl + half * 8;
                        __half* pr = Ob + (size_t)rg * (2 * CI) + cg;
                        *(uint32_t*)(pr)      = pack_h2(h0, h1);
                        *(uint32_t*)(pr + CI) = pack_h2(l0, l1);
                    }
                }
        } else {
            // Fused 2x2 maxpool epilogue (windows are tile-local).
            float (*stage)[33] = (float(*)[33])sm;
            const float* bias = (which == 1) ? p1 : p2;
            const int t_band = blockIdx.y;
#pragma unroll 1
            for (int cg2 = 0; cg2 < 4; ++cg2) {
                __syncthreads();
                if ((wid >> 1) == cg2) {
#pragma unroll
                    for (int mi = 0; mi < 4; ++mi)
#pragma unroll
                        for (int ni = 0; ni < 4; ++ni) {
                            const int r = m_base + mi * 16 + rl;
                            const int c = ni * 8 + cl;
                            stage[r][c]     = acc[mi][ni][0];
                            stage[r][c + 1] = acc[mi][ni][1];
                            stage[r + 8][c]     = acc[mi][ni][2];
                            stage[r + 8][c + 1] = acc[mi][ni][3];
                        }
                }
                __syncthreads();
                if (which == 1) {
                    const int c = tid & 31, pw0 = (tid >> 5) * 4;
                    const int ci = cg2 * 32 + c;
#pragma unroll
                    for (int j = 0; j < 4; ++j) {
                        const int pw = pw0 + j;
                        float v = fmaxf(fmaxf(stage[2 * pw][c], stage[2 * pw + 1][c]),
                                        fmaxf(stage[2 * pw + 64][c], stage[2 * pw + 65][c]))
                                  + bias[ci];
                        __half h = __float2half_rn(v);
                        __half l = __float2half_rn(v - __half2float(h));
                        const int m = t_band * 32 + pw;
                        __half* pr = d_phiP2 + ((size_t)b * NPOOL + m) * (2 * CI);
                        pr[ci] = h; pr[CI + ci] = l;
                    }
                } else {
                    const int pw = tid & 31, c0v = (tid >> 5) * 4;
                    const int m = t_band * 32 + pw;
#pragma unroll
                    for (int j = 0; j < 4; ++j) {
                        const int c = c0v + j, ci = cg2 * 32 + c;
                        float v = fmaxf(fmaxf(stage[2 * pw][c], stage[2 * pw + 1][c]),
                                        fmaxf(stage[2 * pw + 64][c], stage[2 * pw + 65][c]))
                                  + bias[ci];
                        d_gPh[((size_t)b * CI + ci) * NPOOL + m] = __float2half_rn(v);
                    }
                }
            }
        }
    }
}

// ============ flash kernel (R16 shape; 3-deep S pipeline; x4 B fragments) ========
#define FL_PITCH1 144
#define FPP 272
#define FS_A    0
#define FS_B    (FS_A + 3 * 18432)          // 55296
#define FS_PH   (FS_B + 3 * 18432)          // 110592
#define FS_GH   (FS_PH + 34816)             // 145408
#define FS_RED  (FS_GH + 34816)             // 180224
#define FS_RMAX (FS_RED + 2048)
#define FS_RSUM (FS_RMAX + 512)
#define FS_RSC  (FS_RSUM + 512)
#define FS_RBC  (FS_RSC + 512)
#define FL_SMEM (FS_RBC + 512)              // ~184 KB

__global__ __launch_bounds__(512, 1) void flash_kernel()
{
    extern __shared__ __align__(16) char sm[];
    const uint32_t smb = smem_u32(sm);
    float* red  = (float*)(sm + FS_RED);
    float* rmax = (float*)(sm + FS_RMAX);
    float* rsum = (float*)(sm + FS_RSUM);
    float* rsc  = (float*)(sm + FS_RSC);
    float* rbc  = (float*)(sm + FS_RBC);

    const int tid = threadIdx.x, wid = tid >> 5, lid = tid & 31;
    const int b = blockIdx.y;
    const int n0 = blockIdx.x * 128;
    const int mrow = (wid & 3) * 32;
    const int ncol = (wid >> 2) * 32;
    const int nwg = wid >> 2;
    const int rl = lid >> 2, cl = 2 * (lid & 3);

    const __half* At = d_th2 + (size_t)b * NPIX * 256 + (size_t)n0 * 256;
    const __half* Pt = d_phiP2 + (size_t)b * NPOOL * 256;
    const __half* Gh = d_gPh + (size_t)b * CI * NPOOL;

    if (tid < 128) { rmax[tid] = -1e30f; rsum[tid] = 0.f; }
    __syncthreads();

    const uint32_t a1 = (uint32_t)((mrow + (lid & 15)) * FL_PITCH1 + (lid >> 4) * 16);
    const uint32_t b1x4 = (uint32_t)((ncol + (lid & 7) + ((lid >> 4) << 3)) * FL_PITCH1
                                     + ((lid >> 3) & 1) * 16);
    const uint32_t a2 = (uint32_t)((mrow + (lid & 15)) * FPP + (lid >> 4) * 16);
    const uint32_t b2x4 = (uint32_t)((ncol + (lid & 7) + ((lid >> 4) << 3)) * FPP
                                     + ((lid >> 3) & 1) * 16);

    float accY[2][4][4] = {};

    for (int mt = 0; mt < 8; ++mt) {
        const int m0 = mt * 128;

        { // g tile (hi only), 128ci x 128m — group G
            const uint32_t gh = smb + FS_GH;
#pragma unroll
            for (int t = 0; t < 4; ++t) {
                int j = tid + 512 * t;
                int row = j >> 4, seg = j & 15;
                uint32_t dst = (uint32_t)(row * FPP + seg * 16);
                CP16(gh + dst, Gh + (size_t)row * NPOOL + m0 + seg * 8);
            }
            CP_COMMIT();
        }

        auto issue1 = [&](int ch) {
            const int p = ch >> 1, kk = ch & 1;
            const int aK = (p == 1 ? 128 : 0) + kk * 64;
            const int bK = (p == 2 ? 128 : 0) + kk * 64;
            const uint32_t sa = smb + FS_A + (uint32_t)(ch % 3) * 18432;
            const uint32_t sbb = smb + FS_B + (uint32_t)(ch % 3) * 18432;
#pragma unroll
            for (int t = 0; t < 2; ++t) {
                int j = tid + 512 * t;
                int row = j >> 3, seg = j & 7;
                uint32_t dst = (uint32_t)(row * FL_PITCH1 + seg * 16);
                CP16(sa + dst, At + (size_t)row * 256 + aK + seg * 8);
                CP16(sbb + dst, Pt + (size_t)(m0 + row) * 256 + bK + seg * 8);
            }
            CP_COMMIT();
        };

        float accS[2][4][4] = {};
        issue1(0);
        issue1(1);
        for (int ch = 0; ch < 6; ++ch) {
            if (ch + 1 < 6) CP_WAIT1(); else CP_WAIT0();
            __syncthreads();
            if (ch + 2 < 6) issue1(ch + 2);
            const uint32_t sa = smb + FS_A + (uint32_t)(ch % 3) * 18432;
            const uint32_t sbb = smb + FS_B + (uint32_t)(ch % 3) * 18432;
#pragma unroll
            for (int ks = 0; ks < 4; ++ks) {
                uint32_t afr[2][4], b4r[2][4];
#pragma unroll
                for (int mi = 0; mi < 2; ++mi) ldsm_x4(afr[mi], sa + a1 + mi * 16 * FL_PITCH1 + ks * 32);
                ldsm_x4(b4r[0], sbb + b1x4 + ks * 32);                       // ni 0,1
                ldsm_x4(b4r[1], sbb + b1x4 + 16 * FL_PITCH1 + ks * 32);      // ni 2,3
#pragma unroll
                for (int mi = 0; mi < 2; ++mi)
#pragma unroll
                    for (int ni = 0; ni < 4; ++ni)
                        mma16816(accS[mi][ni], afr[mi], &b4r[ni >> 1][(ni & 1) * 2]);
            }
        }

        // ---- online softmax ----
#pragma unroll
        for (int mi = 0; mi < 2; ++mi)
#pragma unroll
            for (int half = 0; half < 2; ++half) {
                float v = -1e30f;
#pragma unroll
                for (int ni = 0; ni < 4; ++ni)
                    v = fmaxf(v, fmaxf(accS[mi][ni][2 * half], accS[mi][ni][2 * half + 1]));
                v = fmaxf(v, __shfl_xor_sync(0xffffffffu, v, 1));
                v = fmaxf(v, __shfl_xor_sync(0xffffffffu, v, 2));
                if ((lid & 3) == 0)
                    red[(mrow + mi * 16 + rl + half * 8) * 4 + nwg] = v;
            }
        __syncthreads();
        if (tid < 128) {
            float mOld = rmax[tid];
            float mNew = fmaxf(fmaxf(red[tid * 4], red[tid * 4 + 1]),
                               fmaxf(red[tid * 4 + 2], red[tid * 4 + 3]));
            mNew = fmaxf(mOld, mNew);
            rbc[tid] = mNew; rsc[tid] = __expf(mOld - mNew); rmax[tid] = mNew;
        }
        __syncthreads();
#pragma unroll
        for (int mi = 0; mi < 2; ++mi)
#pragma unroll
            for (int half = 0; half < 2; ++half) {
                const int r = mrow + mi * 16 + rl + half * 8;
                const float mb = rbc[r];
                const float sc = rsc[r];
                float s = 0.f;
#pragma unroll
                for (int ni = 0; ni < 4; ++ni) {
                    accY[mi][ni][2 * half]     *= sc;
                    accY[mi][ni][2 * half + 1] *= sc;
                    float e0 = __expf(accS[mi][ni][2 * half]     - mb);
                    float e1 = __expf(accS[mi][ni][2 * half + 1] - mb);
                    s += e0 + e1;
                    const uint32_t off = (uint32_t)(r * FPP + (ncol + ni * 8 + cl) * 2);
                    *(uint32_t*)(sm + FS_PH + off) =
                        pack_h2(__float2half_rn(e0), __float2half_rn(e1));
                }
                s += __shfl_xor_sync(0xffffffffu, s, 1);
                s += __shfl_xor_sync(0xffffffffu, s, 2);
                if ((lid & 3) == 0) red[r * 4 + nwg] = s;
            }
        __syncthreads();
        if (tid < 128)
            rsum[tid] = rsum[tid] * rsc[tid] +
                        (red[tid * 4] + red[tid * 4 + 1] + red[tid * 4 + 2] + red[tid * 4 + 3]);

        // ---- phase 2: Y += P * g (1 pass) ----
        {
            const uint32_t ab = smb + FS_PH + a2;
            const uint32_t bb = smb + FS_GH + b2x4;
#pragma unroll
            for (int ks = 0; ks < 8; ++ks) {
                uint32_t afr[2][4], b4r[2][4];
#pragma unroll
                for (int mi = 0; mi < 2; ++mi) ldsm_x4(afr[mi], ab + mi * 16 * FPP + ks * 32);
                ldsm_x4(b4r[0], bb + ks * 32);                 // ni 0,1
                ldsm_x4(b4r[1], bb + 16 * FPP + ks * 32);      // ni 2,3
#pragma unroll
                for (int mi = 0; mi < 2; ++mi)
#pragma unroll
                    for (int ni = 0; ni < 4; ++ni)
                        mma16816(accY[mi][ni], afr[mi], &b4r[ni >> 1][(ni & 1) * 2]);
            }
        }
        __syncthreads();   // protect PH/GH/red before next tile
    }

    // ---- epilogue: normalize, write y single fp16 ----
    __half* Ob = d_y1 + (size_t)b * NPIX * CI + (size_t)n0 * CI;
#pragma unroll
    for (int mi = 0; mi < 2; ++mi)
#pragma unroll
        for (int half = 0; half < 2; ++half) {
            const int r = mrow + mi * 16 + rl + half * 8;
            const float rinv = 1.f / rsum[r];
#pragma unroll
            for (int ni = 0; ni < 4; ++ni) {
                float v0 = accY[mi][ni][2 * half]     * rinv;
                float v1 = accY[mi][ni][2 * half + 1] * rinv;
                *(uint32_t*)(Ob + (size_t)r * CI + (ncol + ni * 8 + cl)) =
                    pack_h2(__float2half_rn(v0), __float2half_rn(v1));
            }
        }
}

// ---------------- merged converts: x transpose-convert + all weight converts ----
// blocks [0, 8192): x tiles — id -> (bx 0..127, by 0..7, bz 0..7), threads 32x8
// blocks [8192, 8704): weights — which = (id-8192)>>7, inner = (id-8192)&127
__global__ __launch_bounds__(256) void conv_all_kernel(
    const float* __restrict__ x,
    const float* __restrict__ th_w, const float* __restrict__ ph_w,
    const float* __restrict__ g_w, const float* __restrict__ W_w)
{
    const int id = blockIdx.x;
    const int tid = threadIdx.x;

    if (id < 8192) {
        __shared__ float t[32][33];
        const int bx = id & 127, by = (id >> 7) & 7, bz = id >> 10;
        const int c0 = by * 32, n0 = bx * 32;
        const int tx = tid & 31, ty = tid >> 5;
        const float* X = x + (size_t)bz * CC * NPIX;
#pragma unroll
        for (int i = 0; i < 4; ++i)
            t[ty + 8 * i][tx] = X[(size_t)(c0 + ty + 8 * i) * NPIX + n0 + tx];
        __syncthreads();
        __half* O = d_x2 + (size_t)bz * NPIX * (2 * CC);
#pragma unroll
        for (int i = 0; i < 4; ++i) {
            int n = n0 + ty + 8 * i;
            float v = t[tx][ty + 8 * i];
            __half h = __float2half_rn(v);
            __half l = __float2half_rn(v - __half2float(h));
            __half* row = O + (size_t)n * (2 * CC) + c0 + tx;
            row[0] = h; row[CC] = l;
        }
    } else {
        const int wid2 = id - 8192;
        const int which = wid2 >> 7;
        const int idx = (wid2 & 127) * 256 + tid;
        if (idx >= CI * CC) return;

        if (which == 3) {
            d_Ww1[idx] = __float2half_rn(W_w[idx]);
            return;
        }
        const float* src = which == 0 ? th_w : which == 1 ? ph_w : g_w;
        __half* dst = d_w2all + (size_t)which * CI * (2 * CC);
        int r = idx / CC, k = idx - r * CC;
        float v = src[idx];
        __half h = __float2half_rn(v);
        __half l = __float2half_rn(v - __half2float(h));
        __half* row = dst + (size_t)r * 2 * CC;
        row[k] = h;
        row[CC + k] = l;
    }
}

// ---------------- launch ----------------------------------------------------------
template <typename T>
static T* sym_addr(const void* sym)
{
    void* p = nullptr;
    cudaGetSymbolAddress(&p, sym);
    return (T*)p;
}

extern "C" void kernel_launch(void* const* d_in, const int* in_sizes, int n_in,
                              void* d_out, int out_size)
{
    const float* x    = (const float*)d_in[0];
    const float* g_w  = (const float*)d_in[1];
    const float* g_b  = (const float*)d_in[2];
    const float* th_w = (const float*)d_in[3];
    const float* th_b = (const float*)d_in[4];
    const float* ph_w = (const float*)d_in[5];
    const float* ph_b = (const float*)d_in[6];
    const float* W_w  = (const float*)d_in[7];
    const float* W_b  = (const float*)d_in[8];
    const float* gam  = (const float*)d_in[9];
    const float* bet  = (const float*)d_in[10];
    const float* mea  = (const float*)d_in[11];
    const float* var  = (const float*)d_in[12];
    float* out = (float*)d_out;

    __half* x2    = sym_addr<__half>(d_x2);
    __half* w2all = sym_addr<__half>(d_w2all);
    __half* Ww1   = sym_addr<__half>(d_Ww1);
    __half* y1    = sym_addr<__half>(d_y1);

    cudaFuncSetAttribute(flash_kernel, cudaFuncAttributeMaxDynamicSharedMemorySize, FL_SMEM);

    // merged converts: x (8192 blocks) + weights (512 blocks), one launch
    conv_all_kernel<<<8704, 256>>>(x, th_w, ph_w, g_w, W_w);

    // merged projections with fused pool for phi/g: z = which*8 + b
    mma_gemm<5><<<dim3(1, 32, 24), 256>>>(
        x2, w2all, (size_t)NPIX * 512, (size_t)CI * 512,
        nullptr, 0, 0, th_b, ph_b, g_b, nullptr, nullptr, nullptr);

    flash_kernel<<<dim3(NPIX / 128, BB), 512, FL_SMEM>>>();

    // out GEMM: A=Ww1 single [c][ci], B=y1 single [n][ci], 1 pass
    mma_gemm<4><<<dim3(NPIX / 128, CC / 128, BB), 256>>>(
        Ww1, y1, 0, (size_t)NPIX * 128,
        out, (size_t)CC * NPIX, NPIX, W_b, gam, bet, mea, var, x);
}